// round 2
// baseline (speedup 1.0000x reference)
#include <cuda_runtime.h>
#include <math.h>

// Problem constants
#define S_LEN   2048
#define D_MODEL 768
#define H_NUM   12
#define HD      64
#define B_SZ    2
#define M_ROWS  (B_SZ * S_LEN)   // 4096

// Scratch (allocation-free rule: __device__ globals)
__device__ float g_q[M_ROWS * D_MODEL];
__device__ float g_k[M_ROWS * D_MODEL];
__device__ float g_v[M_ROWS * D_MODEL];
__device__ float g_ctx[M_ROWS * D_MODEL];

// ---------------------------------------------------------------------------
// GEMM + bias: C[M,768] = A[M,768] @ W[768,768] + bias
// Block tile 128(M) x 64(N), 256 threads, per-thread 8x4, K-chunk 16.
// ---------------------------------------------------------------------------
__global__ __launch_bounds__(256) void gemm_bias_kernel(
    const float* __restrict__ A, const float* __restrict__ W,
    const float* __restrict__ bias, float* __restrict__ C)
{
    __shared__ float As[16][129];   // [k][m], pad -> conflict-free column reads
    __shared__ float Ws[16][64];    // [k][n], row-contiguous -> float4 reads

    const int tid = threadIdx.x;
    const int tx  = tid & 15;       // 0..15  -> n
    const int ty  = tid >> 4;       // 0..15  -> m
    const int m0  = blockIdx.x * 128;
    const int n0  = blockIdx.y * 64;

    // A-tile loader mapping: 512 float4s per 128x16 tile; each thread does 2.
    // float4 covers 4 consecutive k. tid -> (m, k4): k4 = tid & 3, m = tid >> 2
    const int a_k4 = (tid & 3) * 4;
    const int a_m  = tid >> 2;          // 0..63, +64 for second load

    // W-tile loader: 16x64 = 256 float4s; each thread does 1.
    // n fastest: n4 = (tid & 15) * 4, k = tid >> 4
    const int w_n4 = (tid & 15) * 4;
    const int w_k  = tid >> 4;

    float acc[8][4];
#pragma unroll
    for (int i = 0; i < 8; i++)
#pragma unroll
        for (int j = 0; j < 4; j++) acc[i][j] = 0.0f;

    for (int k0 = 0; k0 < D_MODEL; k0 += 16) {
        // Load A tile: 128 rows x 16 k, float4 along k (coalesced 128-bit)
#pragma unroll
        for (int i = 0; i < 2; i++) {
            int m = a_m + i * 64;
            float4 av = *reinterpret_cast<const float4*>(
                &A[(size_t)(m0 + m) * D_MODEL + k0 + a_k4]);
            As[a_k4 + 0][m] = av.x;
            As[a_k4 + 1][m] = av.y;
            As[a_k4 + 2][m] = av.z;
            As[a_k4 + 3][m] = av.w;
        }
        // Load W tile: float4 along n (coalesced, contiguous smem store)
        {
            float4 wv = *reinterpret_cast<const float4*>(
                &W[(size_t)(k0 + w_k) * D_MODEL + n0 + w_n4]);
            *reinterpret_cast<float4*>(&Ws[w_k][w_n4]) = wv;
        }
        __syncthreads();

#pragma unroll
        for (int k = 0; k < 16; k++) {
            float a[8];
#pragma unroll
            for (int i = 0; i < 8; i++) a[i] = As[k][ty * 8 + i];
            float4 wv = *reinterpret_cast<const float4*>(&Ws[k][tx * 4]);
#pragma unroll
            for (int i = 0; i < 8; i++) {
                acc[i][0] += a[i] * wv.x;
                acc[i][1] += a[i] * wv.y;
                acc[i][2] += a[i] * wv.z;
                acc[i][3] += a[i] * wv.w;
            }
        }
        __syncthreads();
    }

    float4 bv = *reinterpret_cast<const float4*>(&bias[n0 + tx * 4]);
#pragma unroll
    for (int i = 0; i < 8; i++) {
        float4 o;
        o.x = acc[i][0] + bv.x;
        o.y = acc[i][1] + bv.y;
        o.z = acc[i][2] + bv.z;
        o.w = acc[i][3] + bv.w;
        *reinterpret_cast<float4*>(
            &C[(size_t)(m0 + ty * 8 + i) * D_MODEL + n0 + tx * 4]) = o;
    }
}

// ---------------------------------------------------------------------------
// Flash attention (fp32, online softmax).
// Block: 256 threads handles 128 queries x 64 head-dim for one (b,h).
// Per thread: 8 query rows x 4 hd cols. Key tiles of 64.
// SMEM (dynamic, ~99.6 KB): Qs[128][65], Ks[64][65], Vs[64][64], Ps[128][65]
// ---------------------------------------------------------------------------
#define BQ  128
#define BKT 64
#define ATTN_SMEM_FLOATS (128 * 65 + 64 * 65 + 64 * 64 + 128 * 65)
#define ATTN_SMEM_BYTES  (ATTN_SMEM_FLOATS * 4)

__global__ __launch_bounds__(256) void attn_kernel(
    const float* __restrict__ Q, const float* __restrict__ K,
    const float* __restrict__ V, float* __restrict__ ctx)
{
    extern __shared__ float sm[];
    float* Qs = sm;               // [128][65]
    float* Ks = Qs + 128 * 65;    // [64][65]
    float* Vs = Ks + 64 * 65;     // [64][64]
    float* Ps = Vs + 64 * 64;     // [128][65]

    const int tid = threadIdx.x;
    const int tx  = tid & 15;     // key-col / hd-col group
    const int ty  = tid >> 4;     // query-row group
    const int q0  = blockIdx.x * BQ;
    const int h   = blockIdx.y;
    const int b   = blockIdx.z;
    const size_t base = (size_t)b * S_LEN * D_MODEL + (size_t)h * HD;

    // Load Q tile: 128 rows x 64 d, float4 along d. 2048 float4s? no:
    // 128*64 = 8192 floats = 2048 float4s, 256 threads -> 8 each
    {
        const int d4 = (tid & 15) * 4;   // 0..60
        const int r0 = tid >> 4;         // 0..15
#pragma unroll
        for (int i = 0; i < 8; i++) {
            int r = r0 + i * 16;
            float4 qv = *reinterpret_cast<const float4*>(
                &Q[base + (size_t)(q0 + r) * D_MODEL + d4]);
            Qs[r * 65 + d4 + 0] = qv.x;
            Qs[r * 65 + d4 + 1] = qv.y;
            Qs[r * 65 + d4 + 2] = qv.z;
            Qs[r * 65 + d4 + 3] = qv.w;
        }
    }

    float m_i[8], l_i[8], acc[8][4];
#pragma unroll
    for (int i = 0; i < 8; i++) {
        m_i[i] = -INFINITY;
        l_i[i] = 0.0f;
#pragma unroll
        for (int j = 0; j < 4; j++) acc[i][j] = 0.0f;
    }
    __syncthreads();

    for (int kt = 0; kt < S_LEN; kt += BKT) {
        // Load K, V tiles: 64 rows x 64 d, float4 along d -> 1024 float4s each,
        // 256 threads -> 4 each
        {
            const int d4 = (tid & 15) * 4;
            const int r0 = tid >> 4;
#pragma unroll
            for (int i = 0; i < 4; i++) {
                int r = r0 + i * 16;
                size_t g = base + (size_t)(kt + r) * D_MODEL + d4;
                float4 kv = *reinterpret_cast<const float4*>(&K[g]);
                Ks[r * 65 + d4 + 0] = kv.x;
                Ks[r * 65 + d4 + 1] = kv.y;
                Ks[r * 65 + d4 + 2] = kv.z;
                Ks[r * 65 + d4 + 3] = kv.w;
                float4 vv = *reinterpret_cast<const float4*>(&V[g]);
                *reinterpret_cast<float4*>(&Vs[r * 64 + d4]) = vv;
            }
        }
        __syncthreads();

        // s = Q @ K^T  (per thread 8x4)
        float s[8][4];
#pragma unroll
        for (int i = 0; i < 8; i++)
#pragma unroll
            for (int j = 0; j < 4; j++) s[i][j] = 0.0f;

#pragma unroll 4
        for (int d = 0; d < HD; d++) {
            float kq[4];
#pragma unroll
            for (int j = 0; j < 4; j++) kq[j] = Ks[(tx * 4 + j) * 65 + d];
#pragma unroll
            for (int i = 0; i < 8; i++) {
                float qv = Qs[(ty * 8 + i) * 65 + d];
                s[i][0] += qv * kq[0];
                s[i][1] += qv * kq[1];
                s[i][2] += qv * kq[2];
                s[i][3] += qv * kq[3];
            }
        }

        // Online softmax: row reductions across the 16 tx lanes via shuffles
        // (lane = (ty&1)*16 + tx, so xor offsets 1,2,4,8 stay within group)
        const float scale = 0.125f;   // 1/sqrt(64)
#pragma unroll
        for (int i = 0; i < 8; i++) {
            float mx = fmaxf(fmaxf(s[i][0], s[i][1]), fmaxf(s[i][2], s[i][3]));
            mx *= scale;  // monotone, same max
#pragma unroll
            for (int o = 1; o < 16; o <<= 1)
                mx = fmaxf(mx, __shfl_xor_sync(0xffffffffu, mx, o));
            float mnew = fmaxf(m_i[i], mx);
            float corr = __expf(m_i[i] - mnew);
            float sum = 0.0f;
#pragma unroll
            for (int j = 0; j < 4; j++) {
                float p = __expf(s[i][j] * scale - mnew);
                sum += p;
                Ps[(ty * 8 + i) * 65 + tx * 4 + j] = p;
            }
#pragma unroll
            for (int o = 1; o < 16; o <<= 1)
                sum += __shfl_xor_sync(0xffffffffu, sum, o);
            l_i[i] = l_i[i] * corr + sum;
            m_i[i] = mnew;
            acc[i][0] *= corr; acc[i][1] *= corr;
            acc[i][2] *= corr; acc[i][3] *= corr;
        }
        __syncthreads();

        // acc += P @ V
#pragma unroll 4
        for (int k = 0; k < BKT; k++) {
            float4 vv = *reinterpret_cast<const float4*>(&Vs[k * 64 + tx * 4]);
#pragma unroll
            for (int i = 0; i < 8; i++) {
                float p = Ps[(ty * 8 + i) * 65 + k];
                acc[i][0] += p * vv.x;
                acc[i][1] += p * vv.y;
                acc[i][2] += p * vv.z;
                acc[i][3] += p * vv.w;
            }
        }
        __syncthreads();
    }

    // Epilogue: normalize and write ctx in [B,S,D] layout (head-interleaved)
#pragma unroll
    for (int i = 0; i < 8; i++) {
        float inv = 1.0f / l_i[i];
        float4 o;
        o.x = acc[i][0] * inv;
        o.y = acc[i][1] * inv;
        o.z = acc[i][2] * inv;
        o.w = acc[i][3] * inv;
        *reinterpret_cast<float4*>(
            &ctx[base + (size_t)(q0 + ty * 8 + i) * D_MODEL + tx * 4]) = o;
    }
}

// ---------------------------------------------------------------------------
// Launch
// ---------------------------------------------------------------------------
extern "C" void kernel_launch(void* const* d_in, const int* in_sizes, int n_in,
                              void* d_out, int out_size)
{
    const float* x  = (const float*)d_in[0];
    const float* Wq = (const float*)d_in[1];
    const float* bq = (const float*)d_in[2];
    const float* Wk = (const float*)d_in[3];
    const float* bk = (const float*)d_in[4];
    const float* Wv = (const float*)d_in[5];
    const float* bv = (const float*)d_in[6];
    const float* Wo = (const float*)d_in[7];
    const float* bo = (const float*)d_in[8];
    float* out = (float*)d_out;

    float *q, *k, *v, *ctx;
    cudaGetSymbolAddress((void**)&q,   g_q);
    cudaGetSymbolAddress((void**)&k,   g_k);
    cudaGetSymbolAddress((void**)&v,   g_v);
    cudaGetSymbolAddress((void**)&ctx, g_ctx);

    cudaFuncSetAttribute(attn_kernel,
                         cudaFuncAttributeMaxDynamicSharedMemorySize,
                         ATTN_SMEM_BYTES);

    dim3 gemm_grid(M_ROWS / 128, D_MODEL / 64);   // 32 x 12

    gemm_bias_kernel<<<gemm_grid, 256>>>(x, Wq, bq, q);
    gemm_bias_kernel<<<gemm_grid, 256>>>(x, Wk, bk, k);
    gemm_bias_kernel<<<gemm_grid, 256>>>(x, Wv, bv, v);

    dim3 attn_grid(S_LEN / BQ, H_NUM, B_SZ);      // 16 x 12 x 2
    attn_kernel<<<attn_grid, 256, ATTN_SMEM_BYTES>>>(q, k, v, ctx);

    gemm_bias_kernel<<<gemm_grid, 256>>>(ctx, Wo, bo, out);
}

// round 4
// speedup vs baseline: 1.3078x; 1.3078x over previous
#include <cuda_runtime.h>
#include <cuda_bf16.h>
#include <cstdint>
#include <math.h>

// Problem constants
#define S_LEN   2048
#define D_MODEL 768
#define H_NUM   12
#define HD      64
#define B_SZ    2
#define M_ROWS  (B_SZ * S_LEN)   // 4096
#define W_ELEMS (D_MODEL * D_MODEL)

// Scratch (allocation-free rule: __device__ globals)
__device__ float g_q[M_ROWS * D_MODEL];
__device__ float g_k[M_ROWS * D_MODEL];
__device__ float g_v[M_ROWS * D_MODEL];
__device__ float g_ctx[M_ROWS * D_MODEL];

// bf16 hi/lo splits
__device__ __nv_bfloat16 g_xh[M_ROWS * D_MODEL];
__device__ __nv_bfloat16 g_xl[M_ROWS * D_MODEL];
__device__ __nv_bfloat16 g_ch[M_ROWS * D_MODEL];
__device__ __nv_bfloat16 g_cl[M_ROWS * D_MODEL];
__device__ __nv_bfloat16 g_wh[4 * W_ELEMS];
__device__ __nv_bfloat16 g_wl[4 * W_ELEMS];

// ===========================================================================
// Warp-MMA helpers (sm_80-era PTX — valid at compute_100; runs as HMMA)
// ===========================================================================
__device__ __forceinline__ uint32_t smem_to_u32(const void* p) {
    uint32_t a;
    asm("{ .reg .u64 t; cvta.to.shared.u64 t, %1; cvt.u32.u64 %0, t; }"
        : "=r"(a) : "l"(p));
    return a;
}

__device__ __forceinline__ void ldsm_x4(uint32_t* r, uint32_t addr) {
    asm volatile(
        "ldmatrix.sync.aligned.m8n8.x4.shared.b16 {%0,%1,%2,%3}, [%4];"
        : "=r"(r[0]), "=r"(r[1]), "=r"(r[2]), "=r"(r[3]) : "r"(addr));
}
__device__ __forceinline__ void ldsm_x4_t(uint32_t* r, uint32_t addr) {
    asm volatile(
        "ldmatrix.sync.aligned.m8n8.x4.trans.shared.b16 {%0,%1,%2,%3}, [%4];"
        : "=r"(r[0]), "=r"(r[1]), "=r"(r[2]), "=r"(r[3]) : "r"(addr));
}
__device__ __forceinline__ void mma_bf16(float* c, const uint32_t* a,
                                         uint32_t b0, uint32_t b1) {
    asm volatile(
        "mma.sync.aligned.m16n8k16.row.col.f32.bf16.bf16.f32 "
        "{%0,%1,%2,%3}, {%4,%5,%6,%7}, {%8,%9}, {%0,%1,%2,%3};"
        : "+f"(c[0]), "+f"(c[1]), "+f"(c[2]), "+f"(c[3])
        : "r"(a[0]), "r"(a[1]), "r"(a[2]), "r"(a[3]), "r"(b0), "r"(b1));
}

// ===========================================================================
// Elementwise fp32 -> (bf16 hi, bf16 lo) split.  lo = x - float(hi).
// ===========================================================================
__global__ __launch_bounds__(256) void split_bf16_kernel(
    const float* __restrict__ in, __nv_bfloat16* __restrict__ hi,
    __nv_bfloat16* __restrict__ lo, int n4)
{
    int i = blockIdx.x * blockDim.x + threadIdx.x;
    if (i >= n4) return;
    float4 v = reinterpret_cast<const float4*>(in)[i];
    __nv_bfloat16 hx = __float2bfloat16(v.x);
    __nv_bfloat16 hy = __float2bfloat16(v.y);
    __nv_bfloat16 hz = __float2bfloat16(v.z);
    __nv_bfloat16 hw = __float2bfloat16(v.w);
    __nv_bfloat162* hp = reinterpret_cast<__nv_bfloat162*>(hi) + 2 * i;
    hp[0] = __nv_bfloat162(hx, hy);
    hp[1] = __nv_bfloat162(hz, hw);
    __nv_bfloat162* lp = reinterpret_cast<__nv_bfloat162*>(lo) + 2 * i;
    lp[0] = __nv_bfloat162(__float2bfloat16(v.x - __bfloat162float(hx)),
                           __float2bfloat16(v.y - __bfloat162float(hy)));
    lp[1] = __nv_bfloat162(__float2bfloat16(v.z - __bfloat162float(hz)),
                           __float2bfloat16(v.w - __bfloat162float(hw)));
}

// ===========================================================================
// HMMA GEMM + bias: C[M,768] = A[M,768] @ W[768,768] + bias
// A given as hi/lo bf16 [m][k]; W as hi/lo bf16 [k][n] (natural layout).
// CTA tile 128(M) x 64(N), BK=64, 8 warps in 4(M) x 2(N), warp tile 32x32.
// 3-term split: C += Ah*Bh + Al*Bh + Ah*Bl  (fp32 accum).
// ===========================================================================
#define BM 128
#define BN 64
#define BK 64
#define LDA 72          // bf16 elems per smem row (pad 8 -> ldmatrix conflict-free)
#define LDB 72
#define SM_AH 0
#define SM_AL (SM_AH + BM * LDA * 2)         // 18432
#define SM_BH (SM_AL + BM * LDA * 2)         // 36864
#define SM_BL (SM_BH + BK * LDB * 2)         // 46080
#define SM_GEMM_TOTAL (SM_BL + BK * LDB * 2) // 55296

__global__ __launch_bounds__(256) void gemm_hmma_kernel(
    const __nv_bfloat16* __restrict__ Ah, const __nv_bfloat16* __restrict__ Al,
    const __nv_bfloat16* __restrict__ Bh, const __nv_bfloat16* __restrict__ Bl,
    const float* __restrict__ bias, float* __restrict__ C)
{
    extern __shared__ char smg[];
    const uint32_t sb = smem_to_u32(smg);
    const int tid  = threadIdx.x;
    const int lane = tid & 31;
    const int w    = tid >> 5;
    const int wm   = w & 3;          // 0..3  (M)
    const int wn   = w >> 2;         // 0..1  (N)
    const int m0   = blockIdx.x * BM;
    const int n0   = blockIdx.y * BN;

    // copy-loop indices
    const int cp_r  = tid >> 3;          // 0..31
    const int cp_k8 = (tid & 7) * 8;     // 0,8,...,56

    // ldmatrix lane addressing
    // A (non-trans): row = lane%16 within 16-row subtile, kc = (lane/16)*8
    const int a_row = (lane & 15);
    const int a_kc  = (lane >> 4) * 8;
    // B (trans, [k][n]): k_loc = lane%16, n_off = (lane/16)*8
    const int b_k   = (lane & 15);
    const int b_n   = (lane >> 4) * 8;

    float c[2][4][4];
#pragma unroll
    for (int mt = 0; mt < 2; mt++)
#pragma unroll
        for (int nt = 0; nt < 4; nt++)
#pragma unroll
            for (int j = 0; j < 4; j++) c[mt][nt][j] = 0.0f;

    for (int ch = 0; ch < D_MODEL / BK; ch++) {
        const int k0 = ch * BK;

        // ---- fill A tiles (hi, lo): 128x64 bf16 each, uint4 = 8 bf16
#pragma unroll
        for (int it = 0; it < 4; it++) {
            const int r = cp_r + it * 32;
            const size_t g = (size_t)(m0 + r) * D_MODEL + k0 + cp_k8;
            *reinterpret_cast<uint4*>(smg + SM_AH + (r * LDA + cp_k8) * 2) =
                *reinterpret_cast<const uint4*>(&Ah[g]);
            *reinterpret_cast<uint4*>(smg + SM_AL + (r * LDA + cp_k8) * 2) =
                *reinterpret_cast<const uint4*>(&Al[g]);
        }
        // ---- fill B tiles (hi, lo): 64(k) x 64(n)
#pragma unroll
        for (int it = 0; it < 2; it++) {
            const int k = cp_r + it * 32;
            const size_t g = (size_t)(k0 + k) * D_MODEL + n0 + cp_k8;
            *reinterpret_cast<uint4*>(smg + SM_BH + (k * LDB + cp_k8) * 2) =
                *reinterpret_cast<const uint4*>(&Bh[g]);
            *reinterpret_cast<uint4*>(smg + SM_BL + (k * LDB + cp_k8) * 2) =
                *reinterpret_cast<const uint4*>(&Bl[g]);
        }
        __syncthreads();

#pragma unroll
        for (int ks = 0; ks < BK / 16; ks++) {
            uint32_t ah0[4], ah1[4], al0[4], al1[4];
            {
                const uint32_t offH0 = SM_AH +
                    ((wm * 32 + a_row) * LDA + ks * 16 + a_kc) * 2;
                ldsm_x4(ah0, sb + offH0);
                ldsm_x4(ah1, sb + offH0 + 16 * LDA * 2);
                const uint32_t offL0 = SM_AL +
                    ((wm * 32 + a_row) * LDA + ks * 16 + a_kc) * 2;
                ldsm_x4(al0, sb + offL0);
                ldsm_x4(al1, sb + offL0 + 16 * LDA * 2);
            }
            uint32_t bh0[4], bh1[4], bl0[4], bl1[4];
            {
                const uint32_t off = ((ks * 16 + b_k) * LDB + wn * 32 + b_n) * 2;
                ldsm_x4_t(bh0, sb + SM_BH + off);
                ldsm_x4_t(bh1, sb + SM_BH + off + 16 * 2);
                ldsm_x4_t(bl0, sb + SM_BL + off);
                ldsm_x4_t(bl1, sb + SM_BL + off + 16 * 2);
            }
#pragma unroll
            for (int nt = 0; nt < 4; nt++) {
                const uint32_t* bhp = (nt < 2) ? bh0 : bh1;
                const uint32_t* blp = (nt < 2) ? bl0 : bl1;
                const int o = (nt & 1) * 2;
                mma_bf16(c[0][nt], ah0, bhp[o], bhp[o + 1]);
                mma_bf16(c[1][nt], ah1, bhp[o], bhp[o + 1]);
                mma_bf16(c[0][nt], al0, bhp[o], bhp[o + 1]);
                mma_bf16(c[1][nt], al1, bhp[o], bhp[o + 1]);
                mma_bf16(c[0][nt], ah0, blp[o], blp[o + 1]);
                mma_bf16(c[1][nt], ah1, blp[o], blp[o + 1]);
            }
        }
        __syncthreads();
    }

    // Epilogue: c-frag -> gmem.  c0,c1: row = base + lane/4, cols n,n+1;
    // c2,c3: row + 8.
#pragma unroll
    for (int mt = 0; mt < 2; mt++) {
        const int mrow = m0 + wm * 32 + mt * 16 + (lane >> 2);
#pragma unroll
        for (int nt = 0; nt < 4; nt++) {
            const int ncol = n0 + wn * 32 + nt * 8 + (lane & 3) * 2;
            const float b0 = bias[ncol], b1 = bias[ncol + 1];
            float2 o0 = make_float2(c[mt][nt][0] + b0, c[mt][nt][1] + b1);
            float2 o1 = make_float2(c[mt][nt][2] + b0, c[mt][nt][3] + b1);
            *reinterpret_cast<float2*>(&C[(size_t)mrow * D_MODEL + ncol]) = o0;
            *reinterpret_cast<float2*>(&C[(size_t)(mrow + 8) * D_MODEL + ncol]) = o1;
        }
    }
}

// ---------------------------------------------------------------------------
// Flash attention (fp32, online softmax) — unchanged from passing R2 kernel.
// ---------------------------------------------------------------------------
#define BQ  128
#define BKT 64
#define ATTN_SMEM_FLOATS (128 * 65 + 64 * 65 + 64 * 64 + 128 * 65)
#define ATTN_SMEM_BYTES  (ATTN_SMEM_FLOATS * 4)

__global__ __launch_bounds__(256) void attn_kernel(
    const float* __restrict__ Q, const float* __restrict__ K,
    const float* __restrict__ V, float* __restrict__ ctx)
{
    extern __shared__ float sm[];
    float* Qs = sm;               // [128][65]
    float* Ks = Qs + 128 * 65;    // [64][65]
    float* Vs = Ks + 64 * 65;     // [64][64]
    float* Ps = Vs + 64 * 64;     // [128][65]

    const int tid = threadIdx.x;
    const int tx  = tid & 15;
    const int ty  = tid >> 4;
    const int q0  = blockIdx.x * BQ;
    const int h   = blockIdx.y;
    const int b   = blockIdx.z;
    const size_t base = (size_t)b * S_LEN * D_MODEL + (size_t)h * HD;

    {
        const int d4 = (tid & 15) * 4;
        const int r0 = tid >> 4;
#pragma unroll
        for (int i = 0; i < 8; i++) {
            int r = r0 + i * 16;
            float4 qv = *reinterpret_cast<const float4*>(
                &Q[base + (size_t)(q0 + r) * D_MODEL + d4]);
            Qs[r * 65 + d4 + 0] = qv.x;
            Qs[r * 65 + d4 + 1] = qv.y;
            Qs[r * 65 + d4 + 2] = qv.z;
            Qs[r * 65 + d4 + 3] = qv.w;
        }
    }

    float m_i[8], l_i[8], acc[8][4];
#pragma unroll
    for (int i = 0; i < 8; i++) {
        m_i[i] = -INFINITY;
        l_i[i] = 0.0f;
#pragma unroll
        for (int j = 0; j < 4; j++) acc[i][j] = 0.0f;
    }
    __syncthreads();

    for (int kt = 0; kt < S_LEN; kt += BKT) {
        {
            const int d4 = (tid & 15) * 4;
            const int r0 = tid >> 4;
#pragma unroll
            for (int i = 0; i < 4; i++) {
                int r = r0 + i * 16;
                size_t g = base + (size_t)(kt + r) * D_MODEL + d4;
                float4 kv = *reinterpret_cast<const float4*>(&K[g]);
                Ks[r * 65 + d4 + 0] = kv.x;
                Ks[r * 65 + d4 + 1] = kv.y;
                Ks[r * 65 + d4 + 2] = kv.z;
                Ks[r * 65 + d4 + 3] = kv.w;
                float4 vv = *reinterpret_cast<const float4*>(&V[g]);
                *reinterpret_cast<float4*>(&Vs[r * 64 + d4]) = vv;
            }
        }
        __syncthreads();

        float s[8][4];
#pragma unroll
        for (int i = 0; i < 8; i++)
#pragma unroll
            for (int j = 0; j < 4; j++) s[i][j] = 0.0f;

#pragma unroll 4
        for (int d = 0; d < HD; d++) {
            float kq[4];
#pragma unroll
            for (int j = 0; j < 4; j++) kq[j] = Ks[(tx * 4 + j) * 65 + d];
#pragma unroll
            for (int i = 0; i < 8; i++) {
                float qv = Qs[(ty * 8 + i) * 65 + d];
                s[i][0] += qv * kq[0];
                s[i][1] += qv * kq[1];
                s[i][2] += qv * kq[2];
                s[i][3] += qv * kq[3];
            }
        }

        const float scale = 0.125f;
#pragma unroll
        for (int i = 0; i < 8; i++) {
            float mx = fmaxf(fmaxf(s[i][0], s[i][1]), fmaxf(s[i][2], s[i][3]));
            mx *= scale;
#pragma unroll
            for (int o = 1; o < 16; o <<= 1)
                mx = fmaxf(mx, __shfl_xor_sync(0xffffffffu, mx, o));
            float mnew = fmaxf(m_i[i], mx);
            float corr = __expf(m_i[i] - mnew);
            float sum = 0.0f;
#pragma unroll
            for (int j = 0; j < 4; j++) {
                float p = __expf(s[i][j] * scale - mnew);
                sum += p;
                Ps[(ty * 8 + i) * 65 + tx * 4 + j] = p;
            }
#pragma unroll
            for (int o = 1; o < 16; o <<= 1)
                sum += __shfl_xor_sync(0xffffffffu, sum, o);
            l_i[i] = l_i[i] * corr + sum;
            m_i[i] = mnew;
            acc[i][0] *= corr; acc[i][1] *= corr;
            acc[i][2] *= corr; acc[i][3] *= corr;
        }
        __syncthreads();

#pragma unroll 4
        for (int k = 0; k < BKT; k++) {
            float4 vv = *reinterpret_cast<const float4*>(&Vs[k * 64 + tx * 4]);
#pragma unroll
            for (int i = 0; i < 8; i++) {
                float p = Ps[(ty * 8 + i) * 65 + k];
                acc[i][0] += p * vv.x;
                acc[i][1] += p * vv.y;
                acc[i][2] += p * vv.z;
                acc[i][3] += p * vv.w;
            }
        }
        __syncthreads();
    }

#pragma unroll
    for (int i = 0; i < 8; i++) {
        float inv = 1.0f / l_i[i];
        float4 o;
        o.x = acc[i][0] * inv;
        o.y = acc[i][1] * inv;
        o.z = acc[i][2] * inv;
        o.w = acc[i][3] * inv;
        *reinterpret_cast<float4*>(
            &ctx[base + (size_t)(q0 + ty * 8 + i) * D_MODEL + tx * 4]) = o;
    }
}

// ---------------------------------------------------------------------------
// Launch
// ---------------------------------------------------------------------------
extern "C" void kernel_launch(void* const* d_in, const int* in_sizes, int n_in,
                              void* d_out, int out_size)
{
    const float* x  = (const float*)d_in[0];
    const float* Wq = (const float*)d_in[1];
    const float* bq = (const float*)d_in[2];
    const float* Wk = (const float*)d_in[3];
    const float* bk = (const float*)d_in[4];
    const float* Wv = (const float*)d_in[5];
    const float* bv = (const float*)d_in[6];
    const float* Wo = (const float*)d_in[7];
    const float* bo = (const float*)d_in[8];
    float* out = (float*)d_out;

    float *q, *k, *v, *ctx;
    cudaGetSymbolAddress((void**)&q,   g_q);
    cudaGetSymbolAddress((void**)&k,   g_k);
    cudaGetSymbolAddress((void**)&v,   g_v);
    cudaGetSymbolAddress((void**)&ctx, g_ctx);

    __nv_bfloat16 *xh, *xl, *ch, *cl, *wh, *wl;
    cudaGetSymbolAddress((void**)&xh, g_xh);
    cudaGetSymbolAddress((void**)&xl, g_xl);
    cudaGetSymbolAddress((void**)&ch, g_ch);
    cudaGetSymbolAddress((void**)&cl, g_cl);
    cudaGetSymbolAddress((void**)&wh, g_wh);
    cudaGetSymbolAddress((void**)&wl, g_wl);

    cudaFuncSetAttribute(gemm_hmma_kernel,
                         cudaFuncAttributeMaxDynamicSharedMemorySize,
                         SM_GEMM_TOTAL);
    cudaFuncSetAttribute(attn_kernel,
                         cudaFuncAttributeMaxDynamicSharedMemorySize,
                         ATTN_SMEM_BYTES);

    const int xn4 = M_ROWS * D_MODEL / 4;        // 786432
    const int wn4 = W_ELEMS / 4;                 // 147456

    // Split x and weights to bf16 hi/lo
    split_bf16_kernel<<<(xn4 + 255) / 256, 256>>>(x, xh, xl, xn4);
    split_bf16_kernel<<<(wn4 + 255) / 256, 256>>>(Wq, wh + 0 * W_ELEMS, wl + 0 * W_ELEMS, wn4);
    split_bf16_kernel<<<(wn4 + 255) / 256, 256>>>(Wk, wh + 1 * W_ELEMS, wl + 1 * W_ELEMS, wn4);
    split_bf16_kernel<<<(wn4 + 255) / 256, 256>>>(Wv, wh + 2 * W_ELEMS, wl + 2 * W_ELEMS, wn4);
    split_bf16_kernel<<<(wn4 + 255) / 256, 256>>>(Wo, wh + 3 * W_ELEMS, wl + 3 * W_ELEMS, wn4);

    dim3 gemm_grid(M_ROWS / BM, D_MODEL / BN);   // 32 x 12

    gemm_hmma_kernel<<<gemm_grid, 256, SM_GEMM_TOTAL>>>(
        xh, xl, wh + 0 * W_ELEMS, wl + 0 * W_ELEMS, bq, q);
    gemm_hmma_kernel<<<gemm_grid, 256, SM_GEMM_TOTAL>>>(
        xh, xl, wh + 1 * W_ELEMS, wl + 1 * W_ELEMS, bk, k);
    gemm_hmma_kernel<<<gemm_grid, 256, SM_GEMM_TOTAL>>>(
        xh, xl, wh + 2 * W_ELEMS, wl + 2 * W_ELEMS, bv, v);

    dim3 attn_grid(S_LEN / BQ, H_NUM, B_SZ);     // 16 x 12 x 2
    attn_kernel<<<attn_grid, 256, ATTN_SMEM_BYTES>>>(q, k, v, ctx);

    split_bf16_kernel<<<(xn4 + 255) / 256, 256>>>(ctx, ch, cl, xn4);
    gemm_hmma_kernel<<<gemm_grid, 256, SM_GEMM_TOTAL>>>(
        ch, cl, wh + 3 * W_ELEMS, wl + 3 * W_ELEMS, bo, out);
}

// round 5
// speedup vs baseline: 2.6893x; 2.0563x over previous
#include <cuda_runtime.h>
#include <cuda_bf16.h>
#include <cstdint>
#include <math.h>

// Problem constants
#define S_LEN   2048
#define D_MODEL 768
#define H_NUM   12
#define HD      64
#define B_SZ    2
#define M_ROWS  (B_SZ * S_LEN)   // 4096
#define W_ELEMS (D_MODEL * D_MODEL)

// Scratch (allocation-free rule: __device__ globals). All bf16 hi/lo pairs.
__device__ __nv_bfloat16 g_xh[M_ROWS * D_MODEL];
__device__ __nv_bfloat16 g_xl[M_ROWS * D_MODEL];
__device__ __nv_bfloat16 g_wh[4 * W_ELEMS];
__device__ __nv_bfloat16 g_wl[4 * W_ELEMS];
__device__ __nv_bfloat16 g_qh[M_ROWS * D_MODEL];
__device__ __nv_bfloat16 g_ql[M_ROWS * D_MODEL];
__device__ __nv_bfloat16 g_kh[M_ROWS * D_MODEL];
__device__ __nv_bfloat16 g_kl[M_ROWS * D_MODEL];
__device__ __nv_bfloat16 g_vh[M_ROWS * D_MODEL];
__device__ __nv_bfloat16 g_vl[M_ROWS * D_MODEL];
__device__ __nv_bfloat16 g_ch[M_ROWS * D_MODEL];
__device__ __nv_bfloat16 g_cl[M_ROWS * D_MODEL];

// ===========================================================================
// Warp-MMA helpers (sm_80-era PTX — valid at compute_100; runs as HMMA)
// ===========================================================================
__device__ __forceinline__ uint32_t smem_to_u32(const void* p) {
    uint32_t a;
    asm("{ .reg .u64 t; cvta.to.shared.u64 t, %1; cvt.u32.u64 %0, t; }"
        : "=r"(a) : "l"(p));
    return a;
}

__device__ __forceinline__ void ldsm_x4(uint32_t* r, uint32_t addr) {
    asm volatile(
        "ldmatrix.sync.aligned.m8n8.x4.shared.b16 {%0,%1,%2,%3}, [%4];"
        : "=r"(r[0]), "=r"(r[1]), "=r"(r[2]), "=r"(r[3]) : "r"(addr));
}
__device__ __forceinline__ void ldsm_x4_t(uint32_t* r, uint32_t addr) {
    asm volatile(
        "ldmatrix.sync.aligned.m8n8.x4.trans.shared.b16 {%0,%1,%2,%3}, [%4];"
        : "=r"(r[0]), "=r"(r[1]), "=r"(r[2]), "=r"(r[3]) : "r"(addr));
}
__device__ __forceinline__ void mma_bf16(float* c, const uint32_t* a,
                                         uint32_t b0, uint32_t b1) {
    asm volatile(
        "mma.sync.aligned.m16n8k16.row.col.f32.bf16.bf16.f32 "
        "{%0,%1,%2,%3}, {%4,%5,%6,%7}, {%8,%9}, {%0,%1,%2,%3};"
        : "+f"(c[0]), "+f"(c[1]), "+f"(c[2]), "+f"(c[3])
        : "r"(a[0]), "r"(a[1]), "r"(a[2]), "r"(a[3]), "r"(b0), "r"(b1));
}
__device__ __forceinline__ uint32_t cvt_bf16x2(float lo, float hi) {
    uint32_t r;
    asm("cvt.rn.bf16x2.f32 %0, %1, %2;" : "=r"(r) : "f"(hi), "f"(lo));
    return r;
}
__device__ __forceinline__ float bf16_rt(float x) {
    return __bfloat162float(__float2bfloat16(x));
}

// ===========================================================================
// Elementwise fp32 -> (bf16 hi, bf16 lo) split.  lo = x - float(hi).
// ===========================================================================
__global__ __launch_bounds__(256) void split_bf16_kernel(
    const float* __restrict__ in, __nv_bfloat16* __restrict__ hi,
    __nv_bfloat16* __restrict__ lo, int n4)
{
    int i = blockIdx.x * blockDim.x + threadIdx.x;
    if (i >= n4) return;
    float4 v = reinterpret_cast<const float4*>(in)[i];
    __nv_bfloat16 hx = __float2bfloat16(v.x);
    __nv_bfloat16 hy = __float2bfloat16(v.y);
    __nv_bfloat16 hz = __float2bfloat16(v.z);
    __nv_bfloat16 hw = __float2bfloat16(v.w);
    __nv_bfloat162* hp = reinterpret_cast<__nv_bfloat162*>(hi) + 2 * i;
    hp[0] = __nv_bfloat162(hx, hy);
    hp[1] = __nv_bfloat162(hz, hw);
    __nv_bfloat162* lp = reinterpret_cast<__nv_bfloat162*>(lo) + 2 * i;
    lp[0] = __nv_bfloat162(__float2bfloat16(v.x - __bfloat162float(hx)),
                           __float2bfloat16(v.y - __bfloat162float(hy)));
    lp[1] = __nv_bfloat162(__float2bfloat16(v.z - __bfloat162float(hz)),
                           __float2bfloat16(v.w - __bfloat162float(hw)));
}

// ===========================================================================
// HMMA GEMM + bias: acc = A[M,768] @ W[768,768]; out = alpha*(acc + bias)
// Output either fp32 (Cf) or split bf16 hi/lo (Ch/Cl) when Cf == nullptr.
// CTA tile 128x64, BK=64, 8 warps 4(M)x2(N), warp tile 32x32.
// 3-term split: C += Ah*Bh + Al*Bh + Ah*Bl  (fp32 accum).
// ===========================================================================
#define BM 128
#define BN 64
#define BK 64
#define LDA 72
#define LDB 72
#define SM_AH 0
#define SM_AL (SM_AH + BM * LDA * 2)         // 18432
#define SM_BH (SM_AL + BM * LDA * 2)         // 36864
#define SM_BL (SM_BH + BK * LDB * 2)         // 46080
#define SM_GEMM_TOTAL (SM_BL + BK * LDB * 2) // 55296

__global__ __launch_bounds__(256) void gemm_hmma_kernel(
    const __nv_bfloat16* __restrict__ Ah, const __nv_bfloat16* __restrict__ Al,
    const __nv_bfloat16* __restrict__ Bh, const __nv_bfloat16* __restrict__ Bl,
    const float* __restrict__ bias, float alpha,
    float* __restrict__ Cf,
    __nv_bfloat16* __restrict__ Ch, __nv_bfloat16* __restrict__ Cl)
{
    extern __shared__ char smg[];
    const uint32_t sb = smem_to_u32(smg);
    const int tid  = threadIdx.x;
    const int lane = tid & 31;
    const int w    = tid >> 5;
    const int wm   = w & 3;
    const int wn   = w >> 2;
    const int m0   = blockIdx.x * BM;
    const int n0   = blockIdx.y * BN;

    const int cp_r  = tid >> 3;
    const int cp_k8 = (tid & 7) * 8;

    const int a_row = (lane & 15);
    const int a_kc  = (lane >> 4) * 8;
    const int b_k   = (lane & 15);
    const int b_n   = (lane >> 4) * 8;

    float c[2][4][4];
#pragma unroll
    for (int mt = 0; mt < 2; mt++)
#pragma unroll
        for (int nt = 0; nt < 4; nt++)
#pragma unroll
            for (int j = 0; j < 4; j++) c[mt][nt][j] = 0.0f;

    for (int ch = 0; ch < D_MODEL / BK; ch++) {
        const int k0 = ch * BK;
#pragma unroll
        for (int it = 0; it < 4; it++) {
            const int r = cp_r + it * 32;
            const size_t g = (size_t)(m0 + r) * D_MODEL + k0 + cp_k8;
            *reinterpret_cast<uint4*>(smg + SM_AH + (r * LDA + cp_k8) * 2) =
                *reinterpret_cast<const uint4*>(&Ah[g]);
            *reinterpret_cast<uint4*>(smg + SM_AL + (r * LDA + cp_k8) * 2) =
                *reinterpret_cast<const uint4*>(&Al[g]);
        }
#pragma unroll
        for (int it = 0; it < 2; it++) {
            const int k = cp_r + it * 32;
            const size_t g = (size_t)(k0 + k) * D_MODEL + n0 + cp_k8;
            *reinterpret_cast<uint4*>(smg + SM_BH + (k * LDB + cp_k8) * 2) =
                *reinterpret_cast<const uint4*>(&Bh[g]);
            *reinterpret_cast<uint4*>(smg + SM_BL + (k * LDB + cp_k8) * 2) =
                *reinterpret_cast<const uint4*>(&Bl[g]);
        }
        __syncthreads();

#pragma unroll
        for (int ks = 0; ks < BK / 16; ks++) {
            uint32_t ah0[4], ah1[4], al0[4], al1[4];
            {
                const uint32_t offH0 = SM_AH +
                    ((wm * 32 + a_row) * LDA + ks * 16 + a_kc) * 2;
                ldsm_x4(ah0, sb + offH0);
                ldsm_x4(ah1, sb + offH0 + 16 * LDA * 2);
                const uint32_t offL0 = SM_AL +
                    ((wm * 32 + a_row) * LDA + ks * 16 + a_kc) * 2;
                ldsm_x4(al0, sb + offL0);
                ldsm_x4(al1, sb + offL0 + 16 * LDA * 2);
            }
            uint32_t bh0[4], bh1[4], bl0[4], bl1[4];
            {
                const uint32_t off = ((ks * 16 + b_k) * LDB + wn * 32 + b_n) * 2;
                ldsm_x4_t(bh0, sb + SM_BH + off);
                ldsm_x4_t(bh1, sb + SM_BH + off + 16 * 2);
                ldsm_x4_t(bl0, sb + SM_BL + off);
                ldsm_x4_t(bl1, sb + SM_BL + off + 16 * 2);
            }
#pragma unroll
            for (int nt = 0; nt < 4; nt++) {
                const uint32_t* bhp = (nt < 2) ? bh0 : bh1;
                const uint32_t* blp = (nt < 2) ? bl0 : bl1;
                const int o = (nt & 1) * 2;
                mma_bf16(c[0][nt], ah0, bhp[o], bhp[o + 1]);
                mma_bf16(c[1][nt], ah1, bhp[o], bhp[o + 1]);
                mma_bf16(c[0][nt], al0, bhp[o], bhp[o + 1]);
                mma_bf16(c[1][nt], al1, bhp[o], bhp[o + 1]);
                mma_bf16(c[0][nt], ah0, blp[o], blp[o + 1]);
                mma_bf16(c[1][nt], ah1, blp[o], blp[o + 1]);
            }
        }
        __syncthreads();
    }

#pragma unroll
    for (int mt = 0; mt < 2; mt++) {
        const int mrow = m0 + wm * 32 + mt * 16 + (lane >> 2);
#pragma unroll
        for (int nt = 0; nt < 4; nt++) {
            const int ncol = n0 + wn * 32 + nt * 8 + (lane & 3) * 2;
            const float b0 = bias[ncol], b1 = bias[ncol + 1];
            if (Cf) {
                float2 o0 = make_float2(c[mt][nt][0] + b0, c[mt][nt][1] + b1);
                float2 o1 = make_float2(c[mt][nt][2] + b0, c[mt][nt][3] + b1);
                *reinterpret_cast<float2*>(&Cf[(size_t)mrow * D_MODEL + ncol]) = o0;
                *reinterpret_cast<float2*>(&Cf[(size_t)(mrow + 8) * D_MODEL + ncol]) = o1;
            } else {
                const float v00 = alpha * (c[mt][nt][0] + b0);
                const float v01 = alpha * (c[mt][nt][1] + b1);
                const float v10 = alpha * (c[mt][nt][2] + b0);
                const float v11 = alpha * (c[mt][nt][3] + b1);
                const size_t g0 = (size_t)mrow * D_MODEL + ncol;
                const size_t g1 = (size_t)(mrow + 8) * D_MODEL + ncol;
                *reinterpret_cast<uint32_t*>(&Ch[g0]) = cvt_bf16x2(v00, v01);
                *reinterpret_cast<uint32_t*>(&Ch[g1]) = cvt_bf16x2(v10, v11);
                *reinterpret_cast<uint32_t*>(&Cl[g0]) =
                    cvt_bf16x2(v00 - bf16_rt(v00), v01 - bf16_rt(v01));
                *reinterpret_cast<uint32_t*>(&Cl[g1]) =
                    cvt_bf16x2(v10 - bf16_rt(v10), v11 - bf16_rt(v11));
            }
        }
    }
}

// ===========================================================================
// HMMA flash attention. Q pre-scaled by 1/8 at projection. All inputs bf16
// hi/lo. Output ctx as bf16 hi/lo. CTA: 256 thr = 8 warps; warp owns 16 query
// rows; key tiles of 64; full 64-key row per warp -> in-warp softmax.
// S = QhKh+QlKh+QhKl;  ctx = PhVh+PlVh+PhVl (fp32 accum, online softmax).
// ===========================================================================
#define AT_LD 72
#define A_SQH 0
#define A_SQL (A_SQH + 128 * AT_LD * 2)   // 18432
#define A_SKH (A_SQL + 128 * AT_LD * 2)   // 36864
#define A_SKL (A_SKH + 64 * AT_LD * 2)    // 46080
#define A_SVH (A_SKL + 64 * AT_LD * 2)    // 55296
#define A_SVL (A_SVH + 64 * AT_LD * 2)    // 64512
#define A_SM_TOTAL (A_SVL + 64 * AT_LD * 2) // 73728

__global__ __launch_bounds__(256, 2) void attn_hmma_kernel(
    const __nv_bfloat16* __restrict__ Qh, const __nv_bfloat16* __restrict__ Ql,
    const __nv_bfloat16* __restrict__ Kh, const __nv_bfloat16* __restrict__ Kl,
    const __nv_bfloat16* __restrict__ Vh, const __nv_bfloat16* __restrict__ Vl,
    __nv_bfloat16* __restrict__ Ch, __nv_bfloat16* __restrict__ Cl)
{
    extern __shared__ char sma[];
    const uint32_t sb = smem_to_u32(sma);
    const int tid  = threadIdx.x;
    const int lane = tid & 31;
    const int w    = tid >> 5;
    const int q0   = blockIdx.x * 128;
    const int h    = blockIdx.y;
    const int b    = blockIdx.z;
    const int hcol = h * HD;
    const size_t rbase = (size_t)b * S_LEN;   // row offset into [4096][768]

    // ldmatrix lane addressing (same as verified GEMM patterns)
    const int l_row = lane & 15;
    const int l_c8  = (lane >> 4) * 8;

    // ---- load Q tile (hi/lo): 128 x 64 bf16, uint4 = 8 elems
    {
        const int r = tid >> 3;             // 0..31
        const int c8 = (tid & 7) * 8;
#pragma unroll
        for (int it = 0; it < 4; it++) {
            const int rr = r + it * 32;
            const size_t g = (rbase + q0 + rr) * D_MODEL + hcol + c8;
            *reinterpret_cast<uint4*>(sma + A_SQH + (rr * AT_LD + c8) * 2) =
                *reinterpret_cast<const uint4*>(&Qh[g]);
            *reinterpret_cast<uint4*>(sma + A_SQL + (rr * AT_LD + c8) * 2) =
                *reinterpret_cast<const uint4*>(&Ql[g]);
        }
    }

    float ctx[8][4];
#pragma unroll
    for (int nt = 0; nt < 8; nt++)
#pragma unroll
        for (int j = 0; j < 4; j++) ctx[nt][j] = 0.0f;
    float m0r = -INFINITY, m1r = -INFINITY, l0r = 0.0f, l1r = 0.0f;

    __syncthreads();

    for (int kt = 0; kt < S_LEN; kt += 64) {
        // ---- load K,V tiles (hi/lo): 64 x 64 each
        {
            const int r = tid >> 3;
            const int c8 = (tid & 7) * 8;
#pragma unroll
            for (int it = 0; it < 2; it++) {
                const int rr = r + it * 32;
                const size_t g = (rbase + kt + rr) * D_MODEL + hcol + c8;
                const uint32_t so = (rr * AT_LD + c8) * 2;
                *reinterpret_cast<uint4*>(sma + A_SKH + so) =
                    *reinterpret_cast<const uint4*>(&Kh[g]);
                *reinterpret_cast<uint4*>(sma + A_SKL + so) =
                    *reinterpret_cast<const uint4*>(&Kl[g]);
                *reinterpret_cast<uint4*>(sma + A_SVH + so) =
                    *reinterpret_cast<const uint4*>(&Vh[g]);
                *reinterpret_cast<uint4*>(sma + A_SVL + so) =
                    *reinterpret_cast<const uint4*>(&Vl[g]);
            }
        }
        __syncthreads();

        // ---- S = Q K^T (scaled already), 3-term split
        float S[8][4];
#pragma unroll
        for (int nt = 0; nt < 8; nt++)
#pragma unroll
            for (int j = 0; j < 4; j++) S[nt][j] = 0.0f;

#pragma unroll
        for (int ks = 0; ks < 4; ks++) {
            uint32_t qh[4], ql[4];
            const uint32_t qoff = ((w * 16 + l_row) * AT_LD + ks * 16 + l_c8) * 2;
            ldsm_x4(qh, sb + A_SQH + qoff);
            ldsm_x4(ql, sb + A_SQL + qoff);
#pragma unroll
            for (int g = 0; g < 4; g++) {
                uint32_t kh[4], kl[4];
                const uint32_t koff = ((g * 16 + l_row) * AT_LD + ks * 16 + l_c8) * 2;
                ldsm_x4(kh, sb + A_SKH + koff);
                ldsm_x4(kl, sb + A_SKL + koff);
                // ntile 2g: keys g*16+0..7 -> frag {r0, r2}; 2g+1 -> {r1, r3}
                mma_bf16(S[2 * g],     qh, kh[0], kh[2]);
                mma_bf16(S[2 * g],     ql, kh[0], kh[2]);
                mma_bf16(S[2 * g],     qh, kl[0], kl[2]);
                mma_bf16(S[2 * g + 1], qh, kh[1], kh[3]);
                mma_bf16(S[2 * g + 1], ql, kh[1], kh[3]);
                mma_bf16(S[2 * g + 1], qh, kl[1], kl[3]);
            }
        }

        // ---- online softmax (rows: lane>>2 and +8; cols spread over lane&3)
        float mx0 = -INFINITY, mx1 = -INFINITY;
#pragma unroll
        for (int nt = 0; nt < 8; nt++) {
            mx0 = fmaxf(mx0, fmaxf(S[nt][0], S[nt][1]));
            mx1 = fmaxf(mx1, fmaxf(S[nt][2], S[nt][3]));
        }
        mx0 = fmaxf(mx0, __shfl_xor_sync(0xffffffffu, mx0, 1));
        mx0 = fmaxf(mx0, __shfl_xor_sync(0xffffffffu, mx0, 2));
        mx1 = fmaxf(mx1, __shfl_xor_sync(0xffffffffu, mx1, 1));
        mx1 = fmaxf(mx1, __shfl_xor_sync(0xffffffffu, mx1, 2));
        const float mn0 = fmaxf(m0r, mx0);
        const float mn1 = fmaxf(m1r, mx1);
        const float cr0 = __expf(m0r - mn0);
        const float cr1 = __expf(m1r - mn1);
        float s0 = 0.0f, s1 = 0.0f;
#pragma unroll
        for (int nt = 0; nt < 8; nt++) {
            S[nt][0] = __expf(S[nt][0] - mn0);
            S[nt][1] = __expf(S[nt][1] - mn0);
            S[nt][2] = __expf(S[nt][2] - mn1);
            S[nt][3] = __expf(S[nt][3] - mn1);
            s0 += S[nt][0] + S[nt][1];
            s1 += S[nt][2] + S[nt][3];
            ctx[nt][0] *= cr0; ctx[nt][1] *= cr0;
            ctx[nt][2] *= cr1; ctx[nt][3] *= cr1;
        }
        s0 += __shfl_xor_sync(0xffffffffu, s0, 1);
        s0 += __shfl_xor_sync(0xffffffffu, s0, 2);
        s1 += __shfl_xor_sync(0xffffffffu, s1, 1);
        s1 += __shfl_xor_sync(0xffffffffu, s1, 2);
        l0r = l0r * cr0 + s0;
        l1r = l1r * cr1 + s1;
        m0r = mn0;
        m1r = mn1;

        // ---- pack P into a-frags (hi + lo); a-frag k-chunk j = ntiles 2j,2j+1
        uint32_t ph[4][4], pl[4][4];
#pragma unroll
        for (int j = 0; j < 4; j++) {
            const float p0 = S[2 * j][0],     p1 = S[2 * j][1];
            const float p2 = S[2 * j][2],     p3 = S[2 * j][3];
            const float p4 = S[2 * j + 1][0], p5 = S[2 * j + 1][1];
            const float p6 = S[2 * j + 1][2], p7 = S[2 * j + 1][3];
            ph[j][0] = cvt_bf16x2(p0, p1);
            ph[j][1] = cvt_bf16x2(p2, p3);
            ph[j][2] = cvt_bf16x2(p4, p5);
            ph[j][3] = cvt_bf16x2(p6, p7);
            pl[j][0] = cvt_bf16x2(p0 - bf16_rt(p0), p1 - bf16_rt(p1));
            pl[j][1] = cvt_bf16x2(p2 - bf16_rt(p2), p3 - bf16_rt(p3));
            pl[j][2] = cvt_bf16x2(p4 - bf16_rt(p4), p5 - bf16_rt(p5));
            pl[j][3] = cvt_bf16x2(p6 - bf16_rt(p6), p7 - bf16_rt(p7));
        }

        // ---- ctx += P V  (V via trans ldsm: B[n=d][k=key])
#pragma unroll
        for (int kc = 0; kc < 4; kc++) {
#pragma unroll
            for (int dg = 0; dg < 4; dg++) {
                uint32_t vh[4], vl[4];
                const uint32_t voff =
                    ((kc * 16 + l_row) * AT_LD + dg * 16 + l_c8) * 2;
                ldsm_x4_t(vh, sb + A_SVH + voff);
                ldsm_x4_t(vl, sb + A_SVL + voff);
                mma_bf16(ctx[2 * dg],     ph[kc], vh[0], vh[1]);
                mma_bf16(ctx[2 * dg],     pl[kc], vh[0], vh[1]);
                mma_bf16(ctx[2 * dg],     ph[kc], vl[0], vl[1]);
                mma_bf16(ctx[2 * dg + 1], ph[kc], vh[2], vh[3]);
                mma_bf16(ctx[2 * dg + 1], pl[kc], vh[2], vh[3]);
                mma_bf16(ctx[2 * dg + 1], ph[kc], vl[2], vl[3]);
            }
        }
        __syncthreads();
    }

    // ---- epilogue: normalize, split, store ctx hi/lo
    const float inv0 = 1.0f / l0r;
    const float inv1 = 1.0f / l1r;
    const int row0 = q0 + w * 16 + (lane >> 2);
#pragma unroll
    for (int nt = 0; nt < 8; nt++) {
        const int col = hcol + nt * 8 + (lane & 3) * 2;
        const float v00 = ctx[nt][0] * inv0, v01 = ctx[nt][1] * inv0;
        const float v10 = ctx[nt][2] * inv1, v11 = ctx[nt][3] * inv1;
        const size_t g0 = (rbase + row0) * D_MODEL + col;
        const size_t g1 = (rbase + row0 + 8) * D_MODEL + col;
        *reinterpret_cast<uint32_t*>(&Ch[g0]) = cvt_bf16x2(v00, v01);
        *reinterpret_cast<uint32_t*>(&Ch[g1]) = cvt_bf16x2(v10, v11);
        *reinterpret_cast<uint32_t*>(&Cl[g0]) =
            cvt_bf16x2(v00 - bf16_rt(v00), v01 - bf16_rt(v01));
        *reinterpret_cast<uint32_t*>(&Cl[g1]) =
            cvt_bf16x2(v10 - bf16_rt(v10), v11 - bf16_rt(v11));
    }
}

// ---------------------------------------------------------------------------
// Launch
// ---------------------------------------------------------------------------
extern "C" void kernel_launch(void* const* d_in, const int* in_sizes, int n_in,
                              void* d_out, int out_size)
{
    const float* x  = (const float*)d_in[0];
    const float* Wq = (const float*)d_in[1];
    const float* bq = (const float*)d_in[2];
    const float* Wk = (const float*)d_in[3];
    const float* bk = (const float*)d_in[4];
    const float* Wv = (const float*)d_in[5];
    const float* bv = (const float*)d_in[6];
    const float* Wo = (const float*)d_in[7];
    const float* bo = (const float*)d_in[8];
    float* out = (float*)d_out;

    __nv_bfloat16 *xh, *xl, *wh, *wl, *qh, *ql, *kh, *kl, *vh, *vl, *ch, *cl;
    cudaGetSymbolAddress((void**)&xh, g_xh);
    cudaGetSymbolAddress((void**)&xl, g_xl);
    cudaGetSymbolAddress((void**)&wh, g_wh);
    cudaGetSymbolAddress((void**)&wl, g_wl);
    cudaGetSymbolAddress((void**)&qh, g_qh);
    cudaGetSymbolAddress((void**)&ql, g_ql);
    cudaGetSymbolAddress((void**)&kh, g_kh);
    cudaGetSymbolAddress((void**)&kl, g_kl);
    cudaGetSymbolAddress((void**)&vh, g_vh);
    cudaGetSymbolAddress((void**)&vl, g_vl);
    cudaGetSymbolAddress((void**)&ch, g_ch);
    cudaGetSymbolAddress((void**)&cl, g_cl);

    cudaFuncSetAttribute(gemm_hmma_kernel,
                         cudaFuncAttributeMaxDynamicSharedMemorySize,
                         SM_GEMM_TOTAL);
    cudaFuncSetAttribute(attn_hmma_kernel,
                         cudaFuncAttributeMaxDynamicSharedMemorySize,
                         A_SM_TOTAL);

    const int xn4 = M_ROWS * D_MODEL / 4;
    const int wn4 = W_ELEMS / 4;

    split_bf16_kernel<<<(xn4 + 255) / 256, 256>>>(x, xh, xl, xn4);
    split_bf16_kernel<<<(wn4 + 255) / 256, 256>>>(Wq, wh + 0 * W_ELEMS, wl + 0 * W_ELEMS, wn4);
    split_bf16_kernel<<<(wn4 + 255) / 256, 256>>>(Wk, wh + 1 * W_ELEMS, wl + 1 * W_ELEMS, wn4);
    split_bf16_kernel<<<(wn4 + 255) / 256, 256>>>(Wv, wh + 2 * W_ELEMS, wl + 2 * W_ELEMS, wn4);
    split_bf16_kernel<<<(wn4 + 255) / 256, 256>>>(Wo, wh + 3 * W_ELEMS, wl + 3 * W_ELEMS, wn4);

    dim3 gemm_grid(M_ROWS / BM, D_MODEL / BN);   // 32 x 12

    gemm_hmma_kernel<<<gemm_grid, 256, SM_GEMM_TOTAL>>>(
        xh, xl, wh + 0 * W_ELEMS, wl + 0 * W_ELEMS, bq, 0.125f,
        nullptr, qh, ql);
    gemm_hmma_kernel<<<gemm_grid, 256, SM_GEMM_TOTAL>>>(
        xh, xl, wh + 1 * W_ELEMS, wl + 1 * W_ELEMS, bk, 1.0f,
        nullptr, kh, kl);
    gemm_hmma_kernel<<<gemm_grid, 256, SM_GEMM_TOTAL>>>(
        xh, xl, wh + 2 * W_ELEMS, wl + 2 * W_ELEMS, bv, 1.0f,
        nullptr, vh, vl);

    dim3 attn_grid(S_LEN / 128, H_NUM, B_SZ);    // 16 x 12 x 2
    attn_hmma_kernel<<<attn_grid, 256, A_SM_TOTAL>>>(
        qh, ql, kh, kl, vh, vl, ch, cl);

    gemm_hmma_kernel<<<gemm_grid, 256, SM_GEMM_TOTAL>>>(
        ch, cl, wh + 3 * W_ELEMS, wl + 3 * W_ELEMS, bo, 1.0f,
        out, nullptr, nullptr);
}

// round 7
// speedup vs baseline: 2.8742x; 1.0687x over previous
#include <cuda_runtime.h>
#include <cuda_bf16.h>
#include <cstdint>
#include <math.h>

// Problem constants
#define S_LEN   2048
#define D_MODEL 768
#define H_NUM   12
#define HD      64
#define B_SZ    2
#define M_ROWS  (B_SZ * S_LEN)   // 4096
#define W_ELEMS (D_MODEL * D_MODEL)

// Scratch (allocation-free rule: __device__ globals). All bf16 hi/lo pairs.
__device__ __nv_bfloat16 g_xh[M_ROWS * D_MODEL];
__device__ __nv_bfloat16 g_xl[M_ROWS * D_MODEL];
__device__ __nv_bfloat16 g_wh[4 * W_ELEMS];
__device__ __nv_bfloat16 g_wl[4 * W_ELEMS];
__device__ __nv_bfloat16 g_qh[M_ROWS * D_MODEL];
__device__ __nv_bfloat16 g_ql[M_ROWS * D_MODEL];
__device__ __nv_bfloat16 g_kh[M_ROWS * D_MODEL];
__device__ __nv_bfloat16 g_kl[M_ROWS * D_MODEL];
__device__ __nv_bfloat16 g_vh[M_ROWS * D_MODEL];
__device__ __nv_bfloat16 g_vl[M_ROWS * D_MODEL];
__device__ __nv_bfloat16 g_ch[M_ROWS * D_MODEL];
__device__ __nv_bfloat16 g_cl[M_ROWS * D_MODEL];

// ===========================================================================
// Warp-MMA + async-copy helpers (sm_80-era PTX — valid at compute_100)
// ===========================================================================
__device__ __forceinline__ uint32_t smem_to_u32(const void* p) {
    uint32_t a;
    asm("{ .reg .u64 t; cvta.to.shared.u64 t, %1; cvt.u32.u64 %0, t; }"
        : "=r"(a) : "l"(p));
    return a;
}
__device__ __forceinline__ void ldsm_x4(uint32_t* r, uint32_t addr) {
    asm volatile(
        "ldmatrix.sync.aligned.m8n8.x4.shared.b16 {%0,%1,%2,%3}, [%4];"
        : "=r"(r[0]), "=r"(r[1]), "=r"(r[2]), "=r"(r[3]) : "r"(addr));
}
__device__ __forceinline__ void ldsm_x4_t(uint32_t* r, uint32_t addr) {
    asm volatile(
        "ldmatrix.sync.aligned.m8n8.x4.trans.shared.b16 {%0,%1,%2,%3}, [%4];"
        : "=r"(r[0]), "=r"(r[1]), "=r"(r[2]), "=r"(r[3]) : "r"(addr));
}
__device__ __forceinline__ void mma_bf16(float* c, const uint32_t* a,
                                         uint32_t b0, uint32_t b1) {
    asm volatile(
        "mma.sync.aligned.m16n8k16.row.col.f32.bf16.bf16.f32 "
        "{%0,%1,%2,%3}, {%4,%5,%6,%7}, {%8,%9}, {%0,%1,%2,%3};"
        : "+f"(c[0]), "+f"(c[1]), "+f"(c[2]), "+f"(c[3])
        : "r"(a[0]), "r"(a[1]), "r"(a[2]), "r"(a[3]), "r"(b0), "r"(b1));
}
__device__ __forceinline__ uint32_t cvt_bf16x2(float lo, float hi) {
    uint32_t r;
    asm("cvt.rn.bf16x2.f32 %0, %1, %2;" : "=r"(r) : "f"(hi), "f"(lo));
    return r;
}
__device__ __forceinline__ float bf16_rt(float x) {
    return __bfloat162float(__float2bfloat16(x));
}
__device__ __forceinline__ void cp_async16(uint32_t dst, const void* src) {
    asm volatile("cp.async.cg.shared.global [%0], [%1], 16;"
                 :: "r"(dst), "l"(src) : "memory");
}
#define CP_COMMIT() asm volatile("cp.async.commit_group;" ::: "memory")
#define CP_WAIT1()  asm volatile("cp.async.wait_group 1;" ::: "memory")
#define CP_WAIT0()  asm volatile("cp.async.wait_group 0;" ::: "memory")

// ===========================================================================
// Elementwise fp32 -> (bf16 hi, bf16 lo) split.  lo = x - float(hi).
// ===========================================================================
__global__ __launch_bounds__(256) void split_bf16_kernel(
    const float* __restrict__ in, __nv_bfloat16* __restrict__ hi,
    __nv_bfloat16* __restrict__ lo, int n4)
{
    int i = blockIdx.x * blockDim.x + threadIdx.x;
    if (i >= n4) return;
    float4 v = reinterpret_cast<const float4*>(in)[i];
    __nv_bfloat16 hx = __float2bfloat16(v.x);
    __nv_bfloat16 hy = __float2bfloat16(v.y);
    __nv_bfloat16 hz = __float2bfloat16(v.z);
    __nv_bfloat16 hw = __float2bfloat16(v.w);
    __nv_bfloat162* hp = reinterpret_cast<__nv_bfloat162*>(hi) + 2 * i;
    hp[0] = __nv_bfloat162(hx, hy);
    hp[1] = __nv_bfloat162(hz, hw);
    __nv_bfloat162* lp = reinterpret_cast<__nv_bfloat162*>(lo) + 2 * i;
    lp[0] = __nv_bfloat162(__float2bfloat16(v.x - __bfloat162float(hx)),
                           __float2bfloat16(v.y - __bfloat162float(hy)));
    lp[1] = __nv_bfloat162(__float2bfloat16(v.z - __bfloat162float(hz)),
                           __float2bfloat16(v.w - __bfloat162float(hw)));
}

// ===========================================================================
// Shared GEMM tiling constants. CTA tile 128x64, BK=64, 8 warps 4(M)x2(N).
// 3-term split: C += Ah*Bh + Al*Bh + Ah*Bl (fp32 accum).
// Double-buffered smem: stage = AH|AL|BH|BL = 55296 B; 2 stages = 110592 B.
// ===========================================================================
#define BM 128
#define BN 64
#define BK 64
#define LDA 72
#define LDB 72
#define GS_AH 0
#define GS_AL 18432
#define GS_BH 36864
#define GS_BL 46080
#define G_STAGE 55296
#define SM_GEMM_TOTAL (2 * G_STAGE)   // 110592

// Issue one K-chunk's cp.async loads into stage `stg` (byte offset).
__device__ __forceinline__ void gemm_issue_loads(
    uint32_t sb, uint32_t stg, int tid, int m0, int n0, int k0,
    const __nv_bfloat16* Ah, const __nv_bfloat16* Al,
    const __nv_bfloat16* Bh, const __nv_bfloat16* Bl)
{
    const int cp_r  = tid >> 3;
    const int cp_k8 = (tid & 7) * 8;
#pragma unroll
    for (int it = 0; it < 4; it++) {
        const int r = cp_r + it * 32;
        const size_t g = (size_t)(m0 + r) * D_MODEL + k0 + cp_k8;
        const uint32_t so = (uint32_t)(r * LDA + cp_k8) * 2;
        cp_async16(sb + stg + GS_AH + so, &Ah[g]);
        cp_async16(sb + stg + GS_AL + so, &Al[g]);
    }
#pragma unroll
    for (int it = 0; it < 2; it++) {
        const int k = cp_r + it * 32;
        const size_t g = (size_t)(k0 + k) * D_MODEL + n0 + cp_k8;
        const uint32_t so = (uint32_t)(k * LDB + cp_k8) * 2;
        cp_async16(sb + stg + GS_BH + so, &Bh[g]);
        cp_async16(sb + stg + GS_BL + so, &Bl[g]);
    }
}

// Core MMA loop over one resident K-chunk.
__device__ __forceinline__ void gemm_compute_chunk(
    uint32_t sb, uint32_t stg, int lane, int wm, int wn, float c[2][4][4])
{
    const int a_row = (lane & 15);
    const int a_kc  = (lane >> 4) * 8;
    const int b_k   = (lane & 15);
    const int b_n   = (lane >> 4) * 8;
#pragma unroll
    for (int ks = 0; ks < BK / 16; ks++) {
        uint32_t ah0[4], ah1[4], al0[4], al1[4];
        {
            const uint32_t offH0 = stg + GS_AH +
                ((wm * 32 + a_row) * LDA + ks * 16 + a_kc) * 2;
            ldsm_x4(ah0, sb + offH0);
            ldsm_x4(ah1, sb + offH0 + 16 * LDA * 2);
            const uint32_t offL0 = stg + GS_AL +
                ((wm * 32 + a_row) * LDA + ks * 16 + a_kc) * 2;
            ldsm_x4(al0, sb + offL0);
            ldsm_x4(al1, sb + offL0 + 16 * LDA * 2);
        }
        uint32_t bh0[4], bh1[4], bl0[4], bl1[4];
        {
            const uint32_t off = ((ks * 16 + b_k) * LDB + wn * 32 + b_n) * 2;
            ldsm_x4_t(bh0, sb + stg + GS_BH + off);
            ldsm_x4_t(bh1, sb + stg + GS_BH + off + 16 * 2);
            ldsm_x4_t(bl0, sb + stg + GS_BL + off);
            ldsm_x4_t(bl1, sb + stg + GS_BL + off + 16 * 2);
        }
#pragma unroll
        for (int nt = 0; nt < 4; nt++) {
            const uint32_t* bhp = (nt < 2) ? bh0 : bh1;
            const uint32_t* blp = (nt < 2) ? bl0 : bl1;
            const int o = (nt & 1) * 2;
            mma_bf16(c[0][nt], ah0, bhp[o], bhp[o + 1]);
            mma_bf16(c[1][nt], ah1, bhp[o], bhp[o + 1]);
            mma_bf16(c[0][nt], al0, bhp[o], bhp[o + 1]);
            mma_bf16(c[1][nt], al1, bhp[o], bhp[o + 1]);
            mma_bf16(c[0][nt], ah0, blp[o], blp[o + 1]);
            mma_bf16(c[1][nt], ah1, blp[o], blp[o + 1]);
        }
    }
}

// ===========================================================================
// Fused QKV GEMM: blockIdx.z selects {Wq->Q(*0.125), Wk->K, Wv->V}.
// Outputs split bf16 hi/lo.
// ===========================================================================
__global__ __launch_bounds__(256) void gemm_qkv_kernel(
    const __nv_bfloat16* __restrict__ Ah, const __nv_bfloat16* __restrict__ Al,
    const __nv_bfloat16* __restrict__ whb, const __nv_bfloat16* __restrict__ wlb,
    const float* __restrict__ bq, const float* __restrict__ bk,
    const float* __restrict__ bv,
    __nv_bfloat16* __restrict__ qh, __nv_bfloat16* __restrict__ ql,
    __nv_bfloat16* __restrict__ kh, __nv_bfloat16* __restrict__ kl,
    __nv_bfloat16* __restrict__ vh, __nv_bfloat16* __restrict__ vl)
{
    extern __shared__ char smg[];
    const uint32_t sb = smem_to_u32(smg);
    const int tid  = threadIdx.x;
    const int lane = tid & 31;
    const int w    = tid >> 5;
    const int wm   = w & 3;
    const int wn   = w >> 2;
    const int m0   = blockIdx.x * BM;
    const int n0   = blockIdx.y * BN;
    const int z    = blockIdx.z;

    const __nv_bfloat16* Bh = whb + (size_t)z * W_ELEMS;
    const __nv_bfloat16* Bl = wlb + (size_t)z * W_ELEMS;
    const float* bias = (z == 0) ? bq : (z == 1) ? bk : bv;
    const float alpha = (z == 0) ? 0.125f : 1.0f;
    __nv_bfloat16* Ch = (z == 0) ? qh : (z == 1) ? kh : vh;
    __nv_bfloat16* Cl = (z == 0) ? ql : (z == 1) ? kl : vl;

    float c[2][4][4];
#pragma unroll
    for (int mt = 0; mt < 2; mt++)
#pragma unroll
        for (int nt = 0; nt < 4; nt++)
#pragma unroll
            for (int j = 0; j < 4; j++) c[mt][nt][j] = 0.0f;

    gemm_issue_loads(sb, 0, tid, m0, n0, 0, Ah, Al, Bh, Bl);
    CP_COMMIT();

    const int NCH = D_MODEL / BK;
    for (int ch = 0; ch < NCH; ch++) {
        const uint32_t cur = (ch & 1) * G_STAGE;
        if (ch + 1 < NCH) {
            gemm_issue_loads(sb, cur ^ G_STAGE, tid, m0, n0,
                             (ch + 1) * BK, Ah, Al, Bh, Bl);
            CP_COMMIT();
            CP_WAIT1();
        } else {
            CP_WAIT0();
        }
        __syncthreads();
        gemm_compute_chunk(sb, cur, lane, wm, wn, c);
        __syncthreads();
    }

#pragma unroll
    for (int mt = 0; mt < 2; mt++) {
        const int mrow = m0 + wm * 32 + mt * 16 + (lane >> 2);
#pragma unroll
        for (int nt = 0; nt < 4; nt++) {
            const int ncol = n0 + wn * 32 + nt * 8 + (lane & 3) * 2;
            const float b0 = bias[ncol], b1 = bias[ncol + 1];
            const float v00 = alpha * (c[mt][nt][0] + b0);
            const float v01 = alpha * (c[mt][nt][1] + b1);
            const float v10 = alpha * (c[mt][nt][2] + b0);
            const float v11 = alpha * (c[mt][nt][3] + b1);
            const size_t g0 = (size_t)mrow * D_MODEL + ncol;
            const size_t g1 = (size_t)(mrow + 8) * D_MODEL + ncol;
            *reinterpret_cast<uint32_t*>(&Ch[g0]) = cvt_bf16x2(v00, v01);
            *reinterpret_cast<uint32_t*>(&Ch[g1]) = cvt_bf16x2(v10, v11);
            *reinterpret_cast<uint32_t*>(&Cl[g0]) =
                cvt_bf16x2(v00 - bf16_rt(v00), v01 - bf16_rt(v01));
            *reinterpret_cast<uint32_t*>(&Cl[g1]) =
                cvt_bf16x2(v10 - bf16_rt(v10), v11 - bf16_rt(v11));
        }
    }
}

// ===========================================================================
// O-projection GEMM: fp32 output = ctx @ Wo + bo.
// ===========================================================================
__global__ __launch_bounds__(256) void gemm_o_kernel(
    const __nv_bfloat16* __restrict__ Ah, const __nv_bfloat16* __restrict__ Al,
    const __nv_bfloat16* __restrict__ Bh, const __nv_bfloat16* __restrict__ Bl,
    const float* __restrict__ bias, float* __restrict__ Cf)
{
    extern __shared__ char smg[];
    const uint32_t sb = smem_to_u32(smg);
    const int tid  = threadIdx.x;
    const int lane = tid & 31;
    const int w    = tid >> 5;
    const int wm   = w & 3;
    const int wn   = w >> 2;
    const int m0   = blockIdx.x * BM;
    const int n0   = blockIdx.y * BN;

    float c[2][4][4];
#pragma unroll
    for (int mt = 0; mt < 2; mt++)
#pragma unroll
        for (int nt = 0; nt < 4; nt++)
#pragma unroll
            for (int j = 0; j < 4; j++) c[mt][nt][j] = 0.0f;

    gemm_issue_loads(sb, 0, tid, m0, n0, 0, Ah, Al, Bh, Bl);
    CP_COMMIT();

    const int NCH = D_MODEL / BK;
    for (int ch = 0; ch < NCH; ch++) {
        const uint32_t cur = (ch & 1) * G_STAGE;
        if (ch + 1 < NCH) {
            gemm_issue_loads(sb, cur ^ G_STAGE, tid, m0, n0,
                             (ch + 1) * BK, Ah, Al, Bh, Bl);
            CP_COMMIT();
            CP_WAIT1();
        } else {
            CP_WAIT0();
        }
        __syncthreads();
        gemm_compute_chunk(sb, cur, lane, wm, wn, c);
        __syncthreads();
    }

#pragma unroll
    for (int mt = 0; mt < 2; mt++) {
        const int mrow = m0 + wm * 32 + mt * 16 + (lane >> 2);
#pragma unroll
        for (int nt = 0; nt < 4; nt++) {
            const int ncol = n0 + wn * 32 + nt * 8 + (lane & 3) * 2;
            const float b0 = bias[ncol], b1 = bias[ncol + 1];
            float2 o0 = make_float2(c[mt][nt][0] + b0, c[mt][nt][1] + b1);
            float2 o1 = make_float2(c[mt][nt][2] + b0, c[mt][nt][3] + b1);
            *reinterpret_cast<float2*>(&Cf[(size_t)mrow * D_MODEL + ncol]) = o0;
            *reinterpret_cast<float2*>(&Cf[(size_t)(mrow + 8) * D_MODEL + ncol]) = o1;
        }
    }
}

// ===========================================================================
// HMMA flash attention, 2-stage cp.async pipeline on K/V tiles.
// Q pre-scaled by 1/8. S = QhKh+QlKh+QhKl; ctx = PhVh+PlVh+PhVl.
// smem: Q (hi+lo) 36864 + 2 stages x (KH|KL|VH|VL) 36864 = 110592 B.
// ===========================================================================
#define AT_LD 72
#define A_QH 0
#define A_QL 18432
#define A_QSZ 36864
#define A_KH 0
#define A_KL 9216
#define A_VH 18432
#define A_VL 27648
#define A_STAGE 36864
#define A_SM_TOTAL (A_QSZ + 2 * A_STAGE)   // 110592

__device__ __forceinline__ void attn_issue_loads(
    uint32_t sb, uint32_t stg, int tid, size_t rbase, int kt, int hcol,
    const __nv_bfloat16* Kh, const __nv_bfloat16* Kl,
    const __nv_bfloat16* Vh, const __nv_bfloat16* Vl)
{
    const int r  = tid >> 3;
    const int c8 = (tid & 7) * 8;
#pragma unroll
    for (int it = 0; it < 2; it++) {
        const int rr = r + it * 32;
        const size_t g = (rbase + kt + rr) * D_MODEL + hcol + c8;
        const uint32_t so = (uint32_t)(rr * AT_LD + c8) * 2;
        cp_async16(sb + stg + A_KH + so, &Kh[g]);
        cp_async16(sb + stg + A_KL + so, &Kl[g]);
        cp_async16(sb + stg + A_VH + so, &Vh[g]);
        cp_async16(sb + stg + A_VL + so, &Vl[g]);
    }
}

__global__ __launch_bounds__(256, 2) void attn_hmma_kernel(
    const __nv_bfloat16* __restrict__ Qh, const __nv_bfloat16* __restrict__ Ql,
    const __nv_bfloat16* __restrict__ Kh, const __nv_bfloat16* __restrict__ Kl,
    const __nv_bfloat16* __restrict__ Vh, const __nv_bfloat16* __restrict__ Vl,
    __nv_bfloat16* __restrict__ Ch, __nv_bfloat16* __restrict__ Cl)
{
    extern __shared__ char sma[];
    const uint32_t sb = smem_to_u32(sma);
    const int tid  = threadIdx.x;
    const int lane = tid & 31;
    const int w    = tid >> 5;
    const int q0   = blockIdx.x * 128;
    const int h    = blockIdx.y;
    const int b    = blockIdx.z;
    const int hcol = h * HD;
    const size_t rbase = (size_t)b * S_LEN;

    const int l_row = lane & 15;
    const int l_c8  = (lane >> 4) * 8;

    // prefetch K/V tile 0 into stage 0
    attn_issue_loads(sb, A_QSZ, tid, rbase, 0, hcol, Kh, Kl, Vh, Vl);
    CP_COMMIT();

    // load Q tile (regular stores; visible after first in-loop syncthreads)
    {
        const int r = tid >> 3;
        const int c8 = (tid & 7) * 8;
#pragma unroll
        for (int it = 0; it < 4; it++) {
            const int rr = r + it * 32;
            const size_t g = (rbase + q0 + rr) * D_MODEL + hcol + c8;
            *reinterpret_cast<uint4*>(sma + A_QH + (rr * AT_LD + c8) * 2) =
                *reinterpret_cast<const uint4*>(&Qh[g]);
            *reinterpret_cast<uint4*>(sma + A_QL + (rr * AT_LD + c8) * 2) =
                *reinterpret_cast<const uint4*>(&Ql[g]);
        }
    }

    float ctx[8][4];
#pragma unroll
    for (int nt = 0; nt < 8; nt++)
#pragma unroll
        for (int j = 0; j < 4; j++) ctx[nt][j] = 0.0f;
    float m0r = -INFINITY, m1r = -INFINITY, l0r = 0.0f, l1r = 0.0f;

    const int NT = S_LEN / 64;
    for (int ti = 0; ti < NT; ti++) {
        const uint32_t cur = A_QSZ + (ti & 1) * A_STAGE;
        if (ti + 1 < NT) {
            attn_issue_loads(sb, A_QSZ + ((ti + 1) & 1) * A_STAGE,
                             tid, rbase, (ti + 1) * 64, hcol, Kh, Kl, Vh, Vl);
            CP_COMMIT();
            CP_WAIT1();
        } else {
            CP_WAIT0();
        }
        __syncthreads();

        // ---- S = Q K^T, 3-term split
        float S[8][4];
#pragma unroll
        for (int nt = 0; nt < 8; nt++)
#pragma unroll
            for (int j = 0; j < 4; j++) S[nt][j] = 0.0f;

#pragma unroll
        for (int ks = 0; ks < 4; ks++) {
            uint32_t qh[4], ql[4];
            const uint32_t qoff = ((w * 16 + l_row) * AT_LD + ks * 16 + l_c8) * 2;
            ldsm_x4(qh, sb + A_QH + qoff);
            ldsm_x4(ql, sb + A_QL + qoff);
#pragma unroll
            for (int g = 0; g < 4; g++) {
                uint32_t kh[4], kl[4];
                const uint32_t koff = cur + A_KH +
                    ((g * 16 + l_row) * AT_LD + ks * 16 + l_c8) * 2;
                ldsm_x4(kh, sb + koff);
                ldsm_x4(kl, sb + koff + (A_KL - A_KH));
                mma_bf16(S[2 * g],     qh, kh[0], kh[2]);
                mma_bf16(S[2 * g],     ql, kh[0], kh[2]);
                mma_bf16(S[2 * g],     qh, kl[0], kl[2]);
                mma_bf16(S[2 * g + 1], qh, kh[1], kh[3]);
                mma_bf16(S[2 * g + 1], ql, kh[1], kh[3]);
                mma_bf16(S[2 * g + 1], qh, kl[1], kl[3]);
            }
        }

        // ---- online softmax
        float mx0 = -INFINITY, mx1 = -INFINITY;
#pragma unroll
        for (int nt = 0; nt < 8; nt++) {
            mx0 = fmaxf(mx0, fmaxf(S[nt][0], S[nt][1]));
            mx1 = fmaxf(mx1, fmaxf(S[nt][2], S[nt][3]));
        }
        mx0 = fmaxf(mx0, __shfl_xor_sync(0xffffffffu, mx0, 1));
        mx0 = fmaxf(mx0, __shfl_xor_sync(0xffffffffu, mx0, 2));
        mx1 = fmaxf(mx1, __shfl_xor_sync(0xffffffffu, mx1, 1));
        mx1 = fmaxf(mx1, __shfl_xor_sync(0xffffffffu, mx1, 2));
        const float mn0 = fmaxf(m0r, mx0);
        const float mn1 = fmaxf(m1r, mx1);
        const float cr0 = __expf(m0r - mn0);
        const float cr1 = __expf(m1r - mn1);
        float s0 = 0.0f, s1 = 0.0f;
#pragma unroll
        for (int nt = 0; nt < 8; nt++) {
            S[nt][0] = __expf(S[nt][0] - mn0);
            S[nt][1] = __expf(S[nt][1] - mn0);
            S[nt][2] = __expf(S[nt][2] - mn1);
            S[nt][3] = __expf(S[nt][3] - mn1);
            s0 += S[nt][0] + S[nt][1];
            s1 += S[nt][2] + S[nt][3];
            ctx[nt][0] *= cr0; ctx[nt][1] *= cr0;
            ctx[nt][2] *= cr1; ctx[nt][3] *= cr1;
        }
        s0 += __shfl_xor_sync(0xffffffffu, s0, 1);
        s0 += __shfl_xor_sync(0xffffffffu, s0, 2);
        s1 += __shfl_xor_sync(0xffffffffu, s1, 1);
        s1 += __shfl_xor_sync(0xffffffffu, s1, 2);
        l0r = l0r * cr0 + s0;
        l1r = l1r * cr1 + s1;
        m0r = mn0;
        m1r = mn1;

        // ---- pack P into a-frags (hi + lo)
        uint32_t ph[4][4], pl[4][4];
#pragma unroll
        for (int j = 0; j < 4; j++) {
            const float p0 = S[2 * j][0],     p1 = S[2 * j][1];
            const float p2 = S[2 * j][2],     p3 = S[2 * j][3];
            const float p4 = S[2 * j + 1][0], p5 = S[2 * j + 1][1];
            const float p6 = S[2 * j + 1][2], p7 = S[2 * j + 1][3];
            ph[j][0] = cvt_bf16x2(p0, p1);
            ph[j][1] = cvt_bf16x2(p2, p3);
            ph[j][2] = cvt_bf16x2(p4, p5);
            ph[j][3] = cvt_bf16x2(p6, p7);
            pl[j][0] = cvt_bf16x2(p0 - bf16_rt(p0), p1 - bf16_rt(p1));
            pl[j][1] = cvt_bf16x2(p2 - bf16_rt(p2), p3 - bf16_rt(p3));
            pl[j][2] = cvt_bf16x2(p4 - bf16_rt(p4), p5 - bf16_rt(p5));
            pl[j][3] = cvt_bf16x2(p6 - bf16_rt(p6), p7 - bf16_rt(p7));
        }

        // ---- ctx += P V
#pragma unroll
        for (int kc = 0; kc < 4; kc++) {
#pragma unroll
            for (int dg = 0; dg < 4; dg++) {
                uint32_t vh[4], vl[4];
                const uint32_t voff = cur + A_VH +
                    ((kc * 16 + l_row) * AT_LD + dg * 16 + l_c8) * 2;
                ldsm_x4_t(vh, sb + voff);
                ldsm_x4_t(vl, sb + voff + (A_VL - A_VH));
                mma_bf16(ctx[2 * dg],     ph[kc], vh[0], vh[1]);
                mma_bf16(ctx[2 * dg],     pl[kc], vh[0], vh[1]);
                mma_bf16(ctx[2 * dg],     ph[kc], vl[0], vl[1]);
                mma_bf16(ctx[2 * dg + 1], ph[kc], vh[2], vh[3]);
                mma_bf16(ctx[2 * dg + 1], pl[kc], vh[2], vh[3]);
                mma_bf16(ctx[2 * dg + 1], ph[kc], vl[2], vl[3]);
            }
        }
        __syncthreads();
    }

    // ---- epilogue
    const float inv0 = 1.0f / l0r;
    const float inv1 = 1.0f / l1r;
    const int row0 = q0 + w * 16 + (lane >> 2);
#pragma unroll
    for (int nt = 0; nt < 8; nt++) {
        const int col = hcol + nt * 8 + (lane & 3) * 2;
        const float v00 = ctx[nt][0] * inv0, v01 = ctx[nt][1] * inv0;
        const float v10 = ctx[nt][2] * inv1, v11 = ctx[nt][3] * inv1;
        const size_t g0 = (rbase + row0) * D_MODEL + col;
        const size_t g1 = (rbase + row0 + 8) * D_MODEL + col;
        *reinterpret_cast<uint32_t*>(&Ch[g0]) = cvt_bf16x2(v00, v01);
        *reinterpret_cast<uint32_t*>(&Ch[g1]) = cvt_bf16x2(v10, v11);
        *reinterpret_cast<uint32_t*>(&Cl[g0]) =
            cvt_bf16x2(v00 - bf16_rt(v00), v01 - bf16_rt(v01));
        *reinterpret_cast<uint32_t*>(&Cl[g1]) =
            cvt_bf16x2(v10 - bf16_rt(v10), v11 - bf16_rt(v11));
    }
}

// ---------------------------------------------------------------------------
// Launch
// ---------------------------------------------------------------------------
extern "C" void kernel_launch(void* const* d_in, const int* in_sizes, int n_in,
                              void* d_out, int out_size)
{
    const float* x  = (const float*)d_in[0];
    const float* Wq = (const float*)d_in[1];
    const float* bq = (const float*)d_in[2];
    const float* Wk = (const float*)d_in[3];
    const float* bk = (const float*)d_in[4];
    const float* Wv = (const float*)d_in[5];
    const float* bv = (const float*)d_in[6];
    const float* Wo = (const float*)d_in[7];
    const float* bo = (const float*)d_in[8];
    float* out = (float*)d_out;

    __nv_bfloat16 *xh, *xl, *wh, *wl, *qh, *ql, *kh, *kl, *vh, *vl, *ch, *cl;
    cudaGetSymbolAddress((void**)&xh, g_xh);
    cudaGetSymbolAddress((void**)&xl, g_xl);
    cudaGetSymbolAddress((void**)&wh, g_wh);
    cudaGetSymbolAddress((void**)&wl, g_wl);
    cudaGetSymbolAddress((void**)&qh, g_qh);
    cudaGetSymbolAddress((void**)&ql, g_ql);
    cudaGetSymbolAddress((void**)&kh, g_kh);
    cudaGetSymbolAddress((void**)&kl, g_kl);
    cudaGetSymbolAddress((void**)&vh, g_vh);
    cudaGetSymbolAddress((void**)&vl, g_vl);
    cudaGetSymbolAddress((void**)&ch, g_ch);
    cudaGetSymbolAddress((void**)&cl, g_cl);

    cudaFuncSetAttribute(gemm_qkv_kernel,
                         cudaFuncAttributeMaxDynamicSharedMemorySize,
                         SM_GEMM_TOTAL);
    cudaFuncSetAttribute(gemm_o_kernel,
                         cudaFuncAttributeMaxDynamicSharedMemorySize,
                         SM_GEMM_TOTAL);
    cudaFuncSetAttribute(attn_hmma_kernel,
                         cudaFuncAttributeMaxDynamicSharedMemorySize,
                         A_SM_TOTAL);

    const int xn4 = M_ROWS * D_MODEL / 4;
    const int wn4 = W_ELEMS / 4;

    split_bf16_kernel<<<(xn4 + 255) / 256, 256>>>(x, xh, xl, xn4);
    split_bf16_kernel<<<(wn4 + 255) / 256, 256>>>(Wq, wh + 0 * W_ELEMS, wl + 0 * W_ELEMS, wn4);
    split_bf16_kernel<<<(wn4 + 255) / 256, 256>>>(Wk, wh + 1 * W_ELEMS, wl + 1 * W_ELEMS, wn4);
    split_bf16_kernel<<<(wn4 + 255) / 256, 256>>>(Wv, wh + 2 * W_ELEMS, wl + 2 * W_ELEMS, wn4);
    split_bf16_kernel<<<(wn4 + 255) / 256, 256>>>(Wo, wh + 3 * W_ELEMS, wl + 3 * W_ELEMS, wn4);

    dim3 qkv_grid(M_ROWS / BM, D_MODEL / BN, 3);   // 32 x 12 x 3
    gemm_qkv_kernel<<<qkv_grid, 256, SM_GEMM_TOTAL>>>(
        xh, xl, wh, wl, bq, bk, bv, qh, ql, kh, kl, vh, vl);

    dim3 attn_grid(S_LEN / 128, H_NUM, B_SZ);      // 16 x 12 x 2
    attn_hmma_kernel<<<attn_grid, 256, A_SM_TOTAL>>>(
        qh, ql, kh, kl, vh, vl, ch, cl);

    dim3 gemm_grid(M_ROWS / BM, D_MODEL / BN);     // 32 x 12
    gemm_o_kernel<<<gemm_grid, 256, SM_GEMM_TOTAL>>>(
        ch, cl, wh + 3 * W_ELEMS, wl + 3 * W_ELEMS, bo, out);
}

// round 8
// speedup vs baseline: 2.8999x; 1.0090x over previous
#include <cuda_runtime.h>
#include <cuda_bf16.h>
#include <cstdint>
#include <math.h>

// Problem constants
#define S_LEN   2048
#define D_MODEL 768
#define H_NUM   12
#define HD      64
#define B_SZ    2
#define M_ROWS  (B_SZ * S_LEN)   // 4096
#define W_ELEMS (D_MODEL * D_MODEL)

// Q pre-scale: 1/sqrt(64) * log2(e)  (softmax done in exp2 domain)
#define ALPHA_Q (0.125f * 1.44269504088896f)

// Scratch (allocation-free rule: __device__ globals). All bf16 hi/lo pairs.
__device__ __nv_bfloat16 g_xh[M_ROWS * D_MODEL];
__device__ __nv_bfloat16 g_xl[M_ROWS * D_MODEL];
__device__ __nv_bfloat16 g_wh[4 * W_ELEMS];
__device__ __nv_bfloat16 g_wl[4 * W_ELEMS];
__device__ __nv_bfloat16 g_qh[M_ROWS * D_MODEL];
__device__ __nv_bfloat16 g_ql[M_ROWS * D_MODEL];
__device__ __nv_bfloat16 g_kh[M_ROWS * D_MODEL];
__device__ __nv_bfloat16 g_kl[M_ROWS * D_MODEL];
__device__ __nv_bfloat16 g_vh[M_ROWS * D_MODEL];
__device__ __nv_bfloat16 g_vl[M_ROWS * D_MODEL];
__device__ __nv_bfloat16 g_ch[M_ROWS * D_MODEL];
__device__ __nv_bfloat16 g_cl[M_ROWS * D_MODEL];

// ===========================================================================
// Warp-MMA + async-copy helpers (sm_80-era PTX — valid at compute_100)
// ===========================================================================
__device__ __forceinline__ uint32_t smem_to_u32(const void* p) {
    uint32_t a;
    asm("{ .reg .u64 t; cvta.to.shared.u64 t, %1; cvt.u32.u64 %0, t; }"
        : "=r"(a) : "l"(p));
    return a;
}
__device__ __forceinline__ void ldsm_x4(uint32_t* r, uint32_t addr) {
    asm volatile(
        "ldmatrix.sync.aligned.m8n8.x4.shared.b16 {%0,%1,%2,%3}, [%4];"
        : "=r"(r[0]), "=r"(r[1]), "=r"(r[2]), "=r"(r[3]) : "r"(addr));
}
__device__ __forceinline__ void ldsm_x4_t(uint32_t* r, uint32_t addr) {
    asm volatile(
        "ldmatrix.sync.aligned.m8n8.x4.trans.shared.b16 {%0,%1,%2,%3}, [%4];"
        : "=r"(r[0]), "=r"(r[1]), "=r"(r[2]), "=r"(r[3]) : "r"(addr));
}
__device__ __forceinline__ void mma_bf16(float* c, const uint32_t* a,
                                         uint32_t b0, uint32_t b1) {
    asm volatile(
        "mma.sync.aligned.m16n8k16.row.col.f32.bf16.bf16.f32 "
        "{%0,%1,%2,%3}, {%4,%5,%6,%7}, {%8,%9}, {%0,%1,%2,%3};"
        : "+f"(c[0]), "+f"(c[1]), "+f"(c[2]), "+f"(c[3])
        : "r"(a[0]), "r"(a[1]), "r"(a[2]), "r"(a[3]), "r"(b0), "r"(b1));
}
__device__ __forceinline__ uint32_t cvt_bf16x2(float lo, float hi) {
    uint32_t r;
    asm("cvt.rn.bf16x2.f32 %0, %1, %2;" : "=r"(r) : "f"(hi), "f"(lo));
    return r;
}
__device__ __forceinline__ float bf16_rt(float x) {
    return __bfloat162float(__float2bfloat16(x));
}
__device__ __forceinline__ void cp_async16(uint32_t dst, const void* src) {
    asm volatile("cp.async.cg.shared.global [%0], [%1], 16;"
                 :: "r"(dst), "l"(src) : "memory");
}
#define CP_COMMIT() asm volatile("cp.async.commit_group;" ::: "memory")
#define CP_WAIT1()  asm volatile("cp.async.wait_group 1;" ::: "memory")
#define CP_WAIT0()  asm volatile("cp.async.wait_group 0;" ::: "memory")

// ===========================================================================
// Fused split: fp32 -> (bf16 hi, bf16 lo) for x + 4 weights in ONE launch.
// blockIdx.y selects tensor. lo = x - float(hi).
// ===========================================================================
__global__ __launch_bounds__(256) void split_all_kernel(
    const float* __restrict__ x,
    const float* __restrict__ Wq, const float* __restrict__ Wk,
    const float* __restrict__ Wv, const float* __restrict__ Wo,
    __nv_bfloat16* __restrict__ xh, __nv_bfloat16* __restrict__ xl,
    __nv_bfloat16* __restrict__ wh, __nv_bfloat16* __restrict__ wl)
{
    const int t = blockIdx.y;
    const float* src;
    __nv_bfloat16 *hi, *lo;
    int n4;
    if (t == 0) { src = x;  hi = xh; lo = xl; n4 = M_ROWS * D_MODEL / 4; }
    else {
        const float* ws[4] = {Wq, Wk, Wv, Wo};
        src = ws[t - 1];
        hi = wh + (size_t)(t - 1) * W_ELEMS;
        lo = wl + (size_t)(t - 1) * W_ELEMS;
        n4 = W_ELEMS / 4;
    }
    int i = blockIdx.x * blockDim.x + threadIdx.x;
    if (i >= n4) return;
    float4 v = reinterpret_cast<const float4*>(src)[i];
    __nv_bfloat16 hx = __float2bfloat16(v.x);
    __nv_bfloat16 hy = __float2bfloat16(v.y);
    __nv_bfloat16 hz = __float2bfloat16(v.z);
    __nv_bfloat16 hw = __float2bfloat16(v.w);
    __nv_bfloat162* hp = reinterpret_cast<__nv_bfloat162*>(hi) + 2 * i;
    hp[0] = __nv_bfloat162(hx, hy);
    hp[1] = __nv_bfloat162(hz, hw);
    __nv_bfloat162* lp = reinterpret_cast<__nv_bfloat162*>(lo) + 2 * i;
    lp[0] = __nv_bfloat162(__float2bfloat16(v.x - __bfloat162float(hx)),
                           __float2bfloat16(v.y - __bfloat162float(hy)));
    lp[1] = __nv_bfloat162(__float2bfloat16(v.z - __bfloat162float(hz)),
                           __float2bfloat16(v.w - __bfloat162float(hw)));
}

// ===========================================================================
// GEMM v2: CTA tile 128(M) x 128(N), BK=32, 8 warps 4(M)x2(N), warp 32x64.
// 3-term split: C += Ah*Bh + Al*Bh + Ah*Bl (fp32 accum). 2-stage cp.async.
// Stage: AH|AL (128x40 bf16 ea) + BH|BL (32x136 bf16 ea) = 37888 B.
// ===========================================================================
#define BM2 128
#define BN2 128
#define BK2 32
#define LDA2 40
#define LDB2 136
#define G2_AH 0
#define G2_AL 10240
#define G2_BH 20480
#define G2_BL 29184
#define G2_STAGE 37888
#define SM_G2_TOTAL (2 * G2_STAGE)   // 75776
#define NCH2 (D_MODEL / BK2)         // 24

__device__ __forceinline__ void gemm2_issue_loads(
    uint32_t sb, uint32_t stg, int tid, int m0, int n0, int k0,
    const __nv_bfloat16* Ah, const __nv_bfloat16* Al,
    const __nv_bfloat16* Bh, const __nv_bfloat16* Bl)
{
#pragma unroll
    for (int it = 0; it < 2; it++) {
        const int idx = tid + it * 256;
        // A: 128 rows x 32 k -> 512 uint4; r = idx>>2, c8 = (idx&3)*8
        {
            const int r = idx >> 2, c8 = (idx & 3) * 8;
            const size_t g = (size_t)(m0 + r) * D_MODEL + k0 + c8;
            const uint32_t so = (uint32_t)(r * LDA2 + c8) * 2;
            cp_async16(sb + stg + G2_AH + so, &Ah[g]);
            cp_async16(sb + stg + G2_AL + so, &Al[g]);
        }
        // B: 32 k x 128 n -> 512 uint4; r = idx>>4, n8 = (idx&15)*8
        {
            const int r = idx >> 4, n8 = (idx & 15) * 8;
            const size_t g = (size_t)(k0 + r) * D_MODEL + n0 + n8;
            const uint32_t so = (uint32_t)(r * LDB2 + n8) * 2;
            cp_async16(sb + stg + G2_BH + so, &Bh[g]);
            cp_async16(sb + stg + G2_BL + so, &Bl[g]);
        }
    }
}

__device__ __forceinline__ void gemm2_compute_chunk(
    uint32_t sb, uint32_t stg, int lane, int wm, int wn, float c[2][8][4])
{
    const int a_row = lane & 15;
    const int a_kc  = (lane >> 4) * 8;
    const int b_k   = lane & 15;
    const int b_n   = (lane >> 4) * 8;
#pragma unroll
    for (int ks = 0; ks < BK2 / 16; ks++) {
        uint32_t ah0[4], ah1[4], al0[4], al1[4];
        {
            const uint32_t offH = stg + G2_AH +
                ((wm * 32 + a_row) * LDA2 + ks * 16 + a_kc) * 2;
            ldsm_x4(ah0, sb + offH);
            ldsm_x4(ah1, sb + offH + 16 * LDA2 * 2);
            const uint32_t offL = stg + G2_AL +
                ((wm * 32 + a_row) * LDA2 + ks * 16 + a_kc) * 2;
            ldsm_x4(al0, sb + offL);
            ldsm_x4(al1, sb + offL + 16 * LDA2 * 2);
        }
#pragma unroll
        for (int nb = 0; nb < 4; nb++) {
            uint32_t bh[4], bl[4];
            const uint32_t offB = stg + G2_BH +
                ((ks * 16 + b_k) * LDB2 + wn * 64 + nb * 16 + b_n) * 2;
            ldsm_x4_t(bh, sb + offB);
            ldsm_x4_t(bl, sb + offB + (G2_BL - G2_BH));
            const int n0t = 2 * nb, n1t = 2 * nb + 1;
            mma_bf16(c[0][n0t], ah0, bh[0], bh[1]);
            mma_bf16(c[1][n0t], ah1, bh[0], bh[1]);
            mma_bf16(c[0][n0t], al0, bh[0], bh[1]);
            mma_bf16(c[1][n0t], al1, bh[0], bh[1]);
            mma_bf16(c[0][n0t], ah0, bl[0], bl[1]);
            mma_bf16(c[1][n0t], ah1, bl[0], bl[1]);
            mma_bf16(c[0][n1t], ah0, bh[2], bh[3]);
            mma_bf16(c[1][n1t], ah1, bh[2], bh[3]);
            mma_bf16(c[0][n1t], al0, bh[2], bh[3]);
            mma_bf16(c[1][n1t], al1, bh[2], bh[3]);
            mma_bf16(c[0][n1t], ah0, bl[2], bl[3]);
            mma_bf16(c[1][n1t], ah1, bl[2], bl[3]);
        }
    }
}

// Fused QKV GEMM: blockIdx.z selects {Wq->Q(*ALPHA_Q), Wk->K, Wv->V}.
__global__ __launch_bounds__(256, 2) void gemm_qkv_kernel(
    const __nv_bfloat16* __restrict__ Ah, const __nv_bfloat16* __restrict__ Al,
    const __nv_bfloat16* __restrict__ whb, const __nv_bfloat16* __restrict__ wlb,
    const float* __restrict__ bq, const float* __restrict__ bk,
    const float* __restrict__ bv,
    __nv_bfloat16* __restrict__ qh, __nv_bfloat16* __restrict__ ql,
    __nv_bfloat16* __restrict__ kh, __nv_bfloat16* __restrict__ kl,
    __nv_bfloat16* __restrict__ vh, __nv_bfloat16* __restrict__ vl)
{
    extern __shared__ char smg[];
    const uint32_t sb = smem_to_u32(smg);
    const int tid  = threadIdx.x;
    const int lane = tid & 31;
    const int w    = tid >> 5;
    const int wm   = w & 3;
    const int wn   = w >> 2;
    const int m0   = blockIdx.x * BM2;
    const int n0   = blockIdx.y * BN2;
    const int z    = blockIdx.z;

    const __nv_bfloat16* Bh = whb + (size_t)z * W_ELEMS;
    const __nv_bfloat16* Bl = wlb + (size_t)z * W_ELEMS;
    const float* bias = (z == 0) ? bq : (z == 1) ? bk : bv;
    const float alpha = (z == 0) ? ALPHA_Q : 1.0f;
    __nv_bfloat16* Ch = (z == 0) ? qh : (z == 1) ? kh : vh;
    __nv_bfloat16* Cl = (z == 0) ? ql : (z == 1) ? kl : vl;

    float c[2][8][4];
#pragma unroll
    for (int mt = 0; mt < 2; mt++)
#pragma unroll
        for (int nt = 0; nt < 8; nt++)
#pragma unroll
            for (int j = 0; j < 4; j++) c[mt][nt][j] = 0.0f;

    gemm2_issue_loads(sb, 0, tid, m0, n0, 0, Ah, Al, Bh, Bl);
    CP_COMMIT();

    for (int ch = 0; ch < NCH2; ch++) {
        const uint32_t cur = (ch & 1) * G2_STAGE;
        if (ch + 1 < NCH2) {
            gemm2_issue_loads(sb, cur ^ G2_STAGE, tid, m0, n0,
                              (ch + 1) * BK2, Ah, Al, Bh, Bl);
            CP_COMMIT();
            CP_WAIT1();
        } else {
            CP_WAIT0();
        }
        __syncthreads();
        gemm2_compute_chunk(sb, cur, lane, wm, wn, c);
        __syncthreads();
    }

#pragma unroll
    for (int mt = 0; mt < 2; mt++) {
        const int mrow = m0 + wm * 32 + mt * 16 + (lane >> 2);
#pragma unroll
        for (int nt = 0; nt < 8; nt++) {
            const int ncol = n0 + wn * 64 + nt * 8 + (lane & 3) * 2;
            const float b0 = bias[ncol], b1 = bias[ncol + 1];
            const float v00 = alpha * (c[mt][nt][0] + b0);
            const float v01 = alpha * (c[mt][nt][1] + b1);
            const float v10 = alpha * (c[mt][nt][2] + b0);
            const float v11 = alpha * (c[mt][nt][3] + b1);
            const size_t g0 = (size_t)mrow * D_MODEL + ncol;
            const size_t g1 = (size_t)(mrow + 8) * D_MODEL + ncol;
            *reinterpret_cast<uint32_t*>(&Ch[g0]) = cvt_bf16x2(v00, v01);
            *reinterpret_cast<uint32_t*>(&Ch[g1]) = cvt_bf16x2(v10, v11);
            *reinterpret_cast<uint32_t*>(&Cl[g0]) =
                cvt_bf16x2(v00 - bf16_rt(v00), v01 - bf16_rt(v01));
            *reinterpret_cast<uint32_t*>(&Cl[g1]) =
                cvt_bf16x2(v10 - bf16_rt(v10), v11 - bf16_rt(v11));
        }
    }
}

// O-projection GEMM: fp32 output = ctx @ Wo + bo.
__global__ __launch_bounds__(256, 2) void gemm_o_kernel(
    const __nv_bfloat16* __restrict__ Ah, const __nv_bfloat16* __restrict__ Al,
    const __nv_bfloat16* __restrict__ Bh, const __nv_bfloat16* __restrict__ Bl,
    const float* __restrict__ bias, float* __restrict__ Cf)
{
    extern __shared__ char smg[];
    const uint32_t sb = smem_to_u32(smg);
    const int tid  = threadIdx.x;
    const int lane = tid & 31;
    const int w    = tid >> 5;
    const int wm   = w & 3;
    const int wn   = w >> 2;
    const int m0   = blockIdx.x * BM2;
    const int n0   = blockIdx.y * BN2;

    float c[2][8][4];
#pragma unroll
    for (int mt = 0; mt < 2; mt++)
#pragma unroll
        for (int nt = 0; nt < 8; nt++)
#pragma unroll
            for (int j = 0; j < 4; j++) c[mt][nt][j] = 0.0f;

    gemm2_issue_loads(sb, 0, tid, m0, n0, 0, Ah, Al, Bh, Bl);
    CP_COMMIT();

    for (int ch = 0; ch < NCH2; ch++) {
        const uint32_t cur = (ch & 1) * G2_STAGE;
        if (ch + 1 < NCH2) {
            gemm2_issue_loads(sb, cur ^ G2_STAGE, tid, m0, n0,
                              (ch + 1) * BK2, Ah, Al, Bh, Bl);
            CP_COMMIT();
            CP_WAIT1();
        } else {
            CP_WAIT0();
        }
        __syncthreads();
        gemm2_compute_chunk(sb, cur, lane, wm, wn, c);
        __syncthreads();
    }

#pragma unroll
    for (int mt = 0; mt < 2; mt++) {
        const int mrow = m0 + wm * 32 + mt * 16 + (lane >> 2);
#pragma unroll
        for (int nt = 0; nt < 8; nt++) {
            const int ncol = n0 + wn * 64 + nt * 8 + (lane & 3) * 2;
            const float b0 = bias[ncol], b1 = bias[ncol + 1];
            float2 o0 = make_float2(c[mt][nt][0] + b0, c[mt][nt][1] + b1);
            float2 o1 = make_float2(c[mt][nt][2] + b0, c[mt][nt][3] + b1);
            *reinterpret_cast<float2*>(&Cf[(size_t)mrow * D_MODEL + ncol]) = o0;
            *reinterpret_cast<float2*>(&Cf[(size_t)(mrow + 8) * D_MODEL + ncol]) = o1;
        }
    }
}

// ===========================================================================
// HMMA flash attention, 2-stage cp.async pipeline on K/V tiles.
// Q pre-scaled by ALPHA_Q (softmax in exp2 domain).
// S = QhKh+QlKh+QhKl; ctx = PhVh+PlVh+PhVl.
// smem: Q (hi+lo) 36864 + 2 stages x (KH|KL|VH|VL) 36864 = 110592 B.
// ===========================================================================
#define AT_LD 72
#define A_QH 0
#define A_QL 18432
#define A_QSZ 36864
#define A_KH 0
#define A_KL 9216
#define A_VH 18432
#define A_VL 27648
#define A_STAGE 36864
#define A_SM_TOTAL (A_QSZ + 2 * A_STAGE)   // 110592

__device__ __forceinline__ void attn_issue_loads(
    uint32_t sb, uint32_t stg, int tid, size_t rbase, int kt, int hcol,
    const __nv_bfloat16* Kh, const __nv_bfloat16* Kl,
    const __nv_bfloat16* Vh, const __nv_bfloat16* Vl)
{
    const int r  = tid >> 3;
    const int c8 = (tid & 7) * 8;
#pragma unroll
    for (int it = 0; it < 2; it++) {
        const int rr = r + it * 32;
        const size_t g = (rbase + kt + rr) * D_MODEL + hcol + c8;
        const uint32_t so = (uint32_t)(rr * AT_LD + c8) * 2;
        cp_async16(sb + stg + A_KH + so, &Kh[g]);
        cp_async16(sb + stg + A_KL + so, &Kl[g]);
        cp_async16(sb + stg + A_VH + so, &Vh[g]);
        cp_async16(sb + stg + A_VL + so, &Vl[g]);
    }
}

__global__ __launch_bounds__(256, 2) void attn_hmma_kernel(
    const __nv_bfloat16* __restrict__ Qh, const __nv_bfloat16* __restrict__ Ql,
    const __nv_bfloat16* __restrict__ Kh, const __nv_bfloat16* __restrict__ Kl,
    const __nv_bfloat16* __restrict__ Vh, const __nv_bfloat16* __restrict__ Vl,
    __nv_bfloat16* __restrict__ Ch, __nv_bfloat16* __restrict__ Cl)
{
    extern __shared__ char sma[];
    const uint32_t sb = smem_to_u32(sma);
    const int tid  = threadIdx.x;
    const int lane = tid & 31;
    const int w    = tid >> 5;
    const int q0   = blockIdx.x * 128;
    const int h    = blockIdx.y;
    const int b    = blockIdx.z;
    const int hcol = h * HD;
    const size_t rbase = (size_t)b * S_LEN;

    const int l_row = lane & 15;
    const int l_c8  = (lane >> 4) * 8;

    attn_issue_loads(sb, A_QSZ, tid, rbase, 0, hcol, Kh, Kl, Vh, Vl);
    CP_COMMIT();

    {
        const int r = tid >> 3;
        const int c8 = (tid & 7) * 8;
#pragma unroll
        for (int it = 0; it < 4; it++) {
            const int rr = r + it * 32;
            const size_t g = (rbase + q0 + rr) * D_MODEL + hcol + c8;
            *reinterpret_cast<uint4*>(sma + A_QH + (rr * AT_LD + c8) * 2) =
                *reinterpret_cast<const uint4*>(&Qh[g]);
            *reinterpret_cast<uint4*>(sma + A_QL + (rr * AT_LD + c8) * 2) =
                *reinterpret_cast<const uint4*>(&Ql[g]);
        }
    }

    float ctx[8][4];
#pragma unroll
    for (int nt = 0; nt < 8; nt++)
#pragma unroll
        for (int j = 0; j < 4; j++) ctx[nt][j] = 0.0f;
    float m0r = -INFINITY, m1r = -INFINITY, l0r = 0.0f, l1r = 0.0f;

    const int NT = S_LEN / 64;
    for (int ti = 0; ti < NT; ti++) {
        const uint32_t cur = A_QSZ + (ti & 1) * A_STAGE;
        if (ti + 1 < NT) {
            attn_issue_loads(sb, A_QSZ + ((ti + 1) & 1) * A_STAGE,
                             tid, rbase, (ti + 1) * 64, hcol, Kh, Kl, Vh, Vl);
            CP_COMMIT();
            CP_WAIT1();
        } else {
            CP_WAIT0();
        }
        __syncthreads();

        // ---- S = Q K^T, 3-term split (log2-domain scores)
        float S[8][4];
#pragma unroll
        for (int nt = 0; nt < 8; nt++)
#pragma unroll
            for (int j = 0; j < 4; j++) S[nt][j] = 0.0f;

#pragma unroll
        for (int ks = 0; ks < 4; ks++) {
            uint32_t qh[4], ql[4];
            const uint32_t qoff = ((w * 16 + l_row) * AT_LD + ks * 16 + l_c8) * 2;
            ldsm_x4(qh, sb + A_QH + qoff);
            ldsm_x4(ql, sb + A_QL + qoff);
#pragma unroll
            for (int g = 0; g < 4; g++) {
                uint32_t kh[4], kl[4];
                const uint32_t koff = cur + A_KH +
                    ((g * 16 + l_row) * AT_LD + ks * 16 + l_c8) * 2;
                ldsm_x4(kh, sb + koff);
                ldsm_x4(kl, sb + koff + (A_KL - A_KH));
                mma_bf16(S[2 * g],     qh, kh[0], kh[2]);
                mma_bf16(S[2 * g],     ql, kh[0], kh[2]);
                mma_bf16(S[2 * g],     qh, kl[0], kl[2]);
                mma_bf16(S[2 * g + 1], qh, kh[1], kh[3]);
                mma_bf16(S[2 * g + 1], ql, kh[1], kh[3]);
                mma_bf16(S[2 * g + 1], qh, kl[1], kl[3]);
            }
        }

        // ---- online softmax (exp2 domain)
        float mx0 = -INFINITY, mx1 = -INFINITY;
#pragma unroll
        for (int nt = 0; nt < 8; nt++) {
            mx0 = fmaxf(mx0, fmaxf(S[nt][0], S[nt][1]));
            mx1 = fmaxf(mx1, fmaxf(S[nt][2], S[nt][3]));
        }
        mx0 = fmaxf(mx0, __shfl_xor_sync(0xffffffffu, mx0, 1));
        mx0 = fmaxf(mx0, __shfl_xor_sync(0xffffffffu, mx0, 2));
        mx1 = fmaxf(mx1, __shfl_xor_sync(0xffffffffu, mx1, 1));
        mx1 = fmaxf(mx1, __shfl_xor_sync(0xffffffffu, mx1, 2));
        const float mn0 = fmaxf(m0r, mx0);
        const float mn1 = fmaxf(m1r, mx1);
        const float cr0 = exp2f(m0r - mn0);
        const float cr1 = exp2f(m1r - mn1);
        float s0 = 0.0f, s1 = 0.0f;
#pragma unroll
        for (int nt = 0; nt < 8; nt++) {
            S[nt][0] = exp2f(S[nt][0] - mn0);
            S[nt][1] = exp2f(S[nt][1] - mn0);
            S[nt][2] = exp2f(S[nt][2] - mn1);
            S[nt][3] = exp2f(S[nt][3] - mn1);
            s0 += S[nt][0] + S[nt][1];
            s1 += S[nt][2] + S[nt][3];
            ctx[nt][0] *= cr0; ctx[nt][1] *= cr0;
            ctx[nt][2] *= cr1; ctx[nt][3] *= cr1;
        }
        s0 += __shfl_xor_sync(0xffffffffu, s0, 1);
        s0 += __shfl_xor_sync(0xffffffffu, s0, 2);
        s1 += __shfl_xor_sync(0xffffffffu, s1, 1);
        s1 += __shfl_xor_sync(0xffffffffu, s1, 2);
        l0r = l0r * cr0 + s0;
        l1r = l1r * cr1 + s1;
        m0r = mn0;
        m1r = mn1;

        // ---- pack P into a-frags (hi + lo)
        uint32_t ph[4][4], pl[4][4];
#pragma unroll
        for (int j = 0; j < 4; j++) {
            const float p0 = S[2 * j][0],     p1 = S[2 * j][1];
            const float p2 = S[2 * j][2],     p3 = S[2 * j][3];
            const float p4 = S[2 * j + 1][0], p5 = S[2 * j + 1][1];
            const float p6 = S[2 * j + 1][2], p7 = S[2 * j + 1][3];
            ph[j][0] = cvt_bf16x2(p0, p1);
            ph[j][1] = cvt_bf16x2(p2, p3);
            ph[j][2] = cvt_bf16x2(p4, p5);
            ph[j][3] = cvt_bf16x2(p6, p7);
            pl[j][0] = cvt_bf16x2(p0 - bf16_rt(p0), p1 - bf16_rt(p1));
            pl[j][1] = cvt_bf16x2(p2 - bf16_rt(p2), p3 - bf16_rt(p3));
            pl[j][2] = cvt_bf16x2(p4 - bf16_rt(p4), p5 - bf16_rt(p5));
            pl[j][3] = cvt_bf16x2(p6 - bf16_rt(p6), p7 - bf16_rt(p7));
        }

        // ---- ctx += P V
#pragma unroll
        for (int kc = 0; kc < 4; kc++) {
#pragma unroll
            for (int dg = 0; dg < 4; dg++) {
                uint32_t vh[4], vl[4];
                const uint32_t voff = cur + A_VH +
                    ((kc * 16 + l_row) * AT_LD + dg * 16 + l_c8) * 2;
                ldsm_x4_t(vh, sb + voff);
                ldsm_x4_t(vl, sb + voff + (A_VL - A_VH));
                mma_bf16(ctx[2 * dg],     ph[kc], vh[0], vh[1]);
                mma_bf16(ctx[2 * dg],     pl[kc], vh[0], vh[1]);
                mma_bf16(ctx[2 * dg],     ph[kc], vl[0], vl[1]);
                mma_bf16(ctx[2 * dg + 1], ph[kc], vh[2], vh[3]);
                mma_bf16(ctx[2 * dg + 1], pl[kc], vh[2], vh[3]);
                mma_bf16(ctx[2 * dg + 1], ph[kc], vl[2], vl[3]);
            }
        }
        __syncthreads();
    }

    // ---- epilogue
    const float inv0 = 1.0f / l0r;
    const float inv1 = 1.0f / l1r;
    const int row0 = q0 + w * 16 + (lane >> 2);
#pragma unroll
    for (int nt = 0; nt < 8; nt++) {
        const int col = hcol + nt * 8 + (lane & 3) * 2;
        const float v00 = ctx[nt][0] * inv0, v01 = ctx[nt][1] * inv0;
        const float v10 = ctx[nt][2] * inv1, v11 = ctx[nt][3] * inv1;
        const size_t g0 = (rbase + row0) * D_MODEL + col;
        const size_t g1 = (rbase + row0 + 8) * D_MODEL + col;
        *reinterpret_cast<uint32_t*>(&Ch[g0]) = cvt_bf16x2(v00, v01);
        *reinterpret_cast<uint32_t*>(&Ch[g1]) = cvt_bf16x2(v10, v11);
        *reinterpret_cast<uint32_t*>(&Cl[g0]) =
            cvt_bf16x2(v00 - bf16_rt(v00), v01 - bf16_rt(v01));
        *reinterpret_cast<uint32_t*>(&Cl[g1]) =
            cvt_bf16x2(v10 - bf16_rt(v10), v11 - bf16_rt(v11));
    }
}

// ---------------------------------------------------------------------------
// Launch
// ---------------------------------------------------------------------------
extern "C" void kernel_launch(void* const* d_in, const int* in_sizes, int n_in,
                              void* d_out, int out_size)
{
    const float* x  = (const float*)d_in[0];
    const float* Wq = (const float*)d_in[1];
    const float* bq = (const float*)d_in[2];
    const float* Wk = (const float*)d_in[3];
    const float* bk = (const float*)d_in[4];
    const float* Wv = (const float*)d_in[5];
    const float* bv = (const float*)d_in[6];
    const float* Wo = (const float*)d_in[7];
    const float* bo = (const float*)d_in[8];
    float* out = (float*)d_out;

    __nv_bfloat16 *xh, *xl, *wh, *wl, *qh, *ql, *kh, *kl, *vh, *vl, *ch, *cl;
    cudaGetSymbolAddress((void**)&xh, g_xh);
    cudaGetSymbolAddress((void**)&xl, g_xl);
    cudaGetSymbolAddress((void**)&wh, g_wh);
    cudaGetSymbolAddress((void**)&wl, g_wl);
    cudaGetSymbolAddress((void**)&qh, g_qh);
    cudaGetSymbolAddress((void**)&ql, g_ql);
    cudaGetSymbolAddress((void**)&kh, g_kh);
    cudaGetSymbolAddress((void**)&kl, g_kl);
    cudaGetSymbolAddress((void**)&vh, g_vh);
    cudaGetSymbolAddress((void**)&vl, g_vl);
    cudaGetSymbolAddress((void**)&ch, g_ch);
    cudaGetSymbolAddress((void**)&cl, g_cl);

    cudaFuncSetAttribute(gemm_qkv_kernel,
                         cudaFuncAttributeMaxDynamicSharedMemorySize,
                         SM_G2_TOTAL);
    cudaFuncSetAttribute(gemm_o_kernel,
                         cudaFuncAttributeMaxDynamicSharedMemorySize,
                         SM_G2_TOTAL);
    cudaFuncSetAttribute(attn_hmma_kernel,
                         cudaFuncAttributeMaxDynamicSharedMemorySize,
                         A_SM_TOTAL);

    // One fused split launch: y=0 -> x (3072 blocks used), y=1..4 -> weights
    dim3 split_grid((M_ROWS * D_MODEL / 4 + 255) / 256, 5);
    split_all_kernel<<<split_grid, 256>>>(x, Wq, Wk, Wv, Wo, xh, xl, wh, wl);

    dim3 qkv_grid(M_ROWS / BM2, D_MODEL / BN2, 3);   // 32 x 6 x 3
    gemm_qkv_kernel<<<qkv_grid, 256, SM_G2_TOTAL>>>(
        xh, xl, wh, wl, bq, bk, bv, qh, ql, kh, kl, vh, vl);

    dim3 attn_grid(S_LEN / 128, H_NUM, B_SZ);        // 16 x 12 x 2
    attn_hmma_kernel<<<attn_grid, 256, A_SM_TOTAL>>>(
        qh, ql, kh, kl, vh, vl, ch, cl);

    dim3 o_grid(M_ROWS / BM2, D_MODEL / BN2);        // 32 x 6
    gemm_o_kernel<<<o_grid, 256, SM_G2_TOTAL>>>(
        ch, cl, wh + 3 * W_ELEMS, wl + 3 * W_ELEMS, bo, out);
}

// round 9
// speedup vs baseline: 2.9374x; 1.0129x over previous
#include <cuda_runtime.h>
#include <cuda_bf16.h>
#include <cstdint>
#include <math.h>

// Problem constants
#define S_LEN   2048
#define D_MODEL 768
#define H_NUM   12
#define HD      64
#define B_SZ    2
#define M_ROWS  (B_SZ * S_LEN)   // 4096
#define W_ELEMS (D_MODEL * D_MODEL)

// Q pre-scale: 1/sqrt(64) * log2(e)  (softmax done in exp2 domain)
#define ALPHA_Q (0.125f * 1.44269504088896f)

// Scratch (allocation-free rule: __device__ globals). All bf16 hi/lo pairs.
__device__ __nv_bfloat16 g_xh[M_ROWS * D_MODEL];
__device__ __nv_bfloat16 g_xl[M_ROWS * D_MODEL];
__device__ __nv_bfloat16 g_wh[4 * W_ELEMS];
__device__ __nv_bfloat16 g_wl[4 * W_ELEMS];
__device__ __nv_bfloat16 g_qh[M_ROWS * D_MODEL];
__device__ __nv_bfloat16 g_ql[M_ROWS * D_MODEL];
__device__ __nv_bfloat16 g_kh[M_ROWS * D_MODEL];
__device__ __nv_bfloat16 g_kl[M_ROWS * D_MODEL];
__device__ __nv_bfloat16 g_vh[M_ROWS * D_MODEL];
__device__ __nv_bfloat16 g_vl[M_ROWS * D_MODEL];
__device__ __nv_bfloat16 g_ch[M_ROWS * D_MODEL];
__device__ __nv_bfloat16 g_cl[M_ROWS * D_MODEL];

// ===========================================================================
// Warp-MMA + async-copy helpers
// ===========================================================================
__device__ __forceinline__ uint32_t smem_to_u32(const void* p) {
    uint32_t a;
    asm("{ .reg .u64 t; cvta.to.shared.u64 t, %1; cvt.u32.u64 %0, t; }"
        : "=r"(a) : "l"(p));
    return a;
}
__device__ __forceinline__ void ldsm_x4(uint32_t* r, uint32_t addr) {
    asm volatile(
        "ldmatrix.sync.aligned.m8n8.x4.shared.b16 {%0,%1,%2,%3}, [%4];"
        : "=r"(r[0]), "=r"(r[1]), "=r"(r[2]), "=r"(r[3]) : "r"(addr));
}
__device__ __forceinline__ void ldsm_x4_t(uint32_t* r, uint32_t addr) {
    asm volatile(
        "ldmatrix.sync.aligned.m8n8.x4.trans.shared.b16 {%0,%1,%2,%3}, [%4];"
        : "=r"(r[0]), "=r"(r[1]), "=r"(r[2]), "=r"(r[3]) : "r"(addr));
}
__device__ __forceinline__ void mma_bf16(float* c, const uint32_t* a,
                                         uint32_t b0, uint32_t b1) {
    asm volatile(
        "mma.sync.aligned.m16n8k16.row.col.f32.bf16.bf16.f32 "
        "{%0,%1,%2,%3}, {%4,%5,%6,%7}, {%8,%9}, {%0,%1,%2,%3};"
        : "+f"(c[0]), "+f"(c[1]), "+f"(c[2]), "+f"(c[3])
        : "r"(a[0]), "r"(a[1]), "r"(a[2]), "r"(a[3]), "r"(b0), "r"(b1));
}
__device__ __forceinline__ uint32_t cvt_bf16x2(float lo, float hi) {
    uint32_t r;
    asm("cvt.rn.bf16x2.f32 %0, %1, %2;" : "=r"(r) : "f"(hi), "f"(lo));
    return r;
}
__device__ __forceinline__ float bf16_rt(float x) {
    return __bfloat162float(__float2bfloat16(x));
}
__device__ __forceinline__ void cp_async16(uint32_t dst, const void* src) {
    asm volatile("cp.async.cg.shared.global [%0], [%1], 16;"
                 :: "r"(dst), "l"(src) : "memory");
}
#define CP_COMMIT() asm volatile("cp.async.commit_group;" ::: "memory")
#define CP_WAIT1()  asm volatile("cp.async.wait_group 1;" ::: "memory")
#define CP_WAIT0()  asm volatile("cp.async.wait_group 0;" ::: "memory")

// ===========================================================================
// Fused split: fp32 -> (bf16 hi, bf16 lo) for x + 4 weights in ONE launch.
// ===========================================================================
__global__ __launch_bounds__(256) void split_all_kernel(
    const float* __restrict__ x,
    const float* __restrict__ Wq, const float* __restrict__ Wk,
    const float* __restrict__ Wv, const float* __restrict__ Wo,
    __nv_bfloat16* __restrict__ xh, __nv_bfloat16* __restrict__ xl,
    __nv_bfloat16* __restrict__ wh, __nv_bfloat16* __restrict__ wl)
{
    const int t = blockIdx.y;
    const float* src;
    __nv_bfloat16 *hi, *lo;
    int n4;
    if (t == 0) { src = x;  hi = xh; lo = xl; n4 = M_ROWS * D_MODEL / 4; }
    else {
        const float* ws[4] = {Wq, Wk, Wv, Wo};
        src = ws[t - 1];
        hi = wh + (size_t)(t - 1) * W_ELEMS;
        lo = wl + (size_t)(t - 1) * W_ELEMS;
        n4 = W_ELEMS / 4;
    }
    int i = blockIdx.x * blockDim.x + threadIdx.x;
    if (i >= n4) return;
    float4 v = reinterpret_cast<const float4*>(src)[i];
    __nv_bfloat16 hx = __float2bfloat16(v.x);
    __nv_bfloat16 hy = __float2bfloat16(v.y);
    __nv_bfloat16 hz = __float2bfloat16(v.z);
    __nv_bfloat16 hw = __float2bfloat16(v.w);
    __nv_bfloat162* hp = reinterpret_cast<__nv_bfloat162*>(hi) + 2 * i;
    hp[0] = __nv_bfloat162(hx, hy);
    hp[1] = __nv_bfloat162(hz, hw);
    __nv_bfloat162* lp = reinterpret_cast<__nv_bfloat162*>(lo) + 2 * i;
    lp[0] = __nv_bfloat162(__float2bfloat16(v.x - __bfloat162float(hx)),
                           __float2bfloat16(v.y - __bfloat162float(hy)));
    lp[1] = __nv_bfloat162(__float2bfloat16(v.z - __bfloat162float(hz)),
                           __float2bfloat16(v.w - __bfloat162float(hw)));
}

// ===========================================================================
// GEMM v2: CTA tile 128(M) x 128(N), BK=32, 8 warps 4(M)x2(N), warp 32x64.
// Three-pass MMA order (hh x16, lh x16, hl x16) -> dep distance 16.
// ===========================================================================
#define BM2 128
#define BN2 128
#define BK2 32
#define LDA2 40
#define LDB2 136
#define G2_AH 0
#define G2_AL 10240
#define G2_BH 20480
#define G2_BL 29184
#define G2_STAGE 37888
#define SM_G2_TOTAL (2 * G2_STAGE)   // 75776
#define NCH2 (D_MODEL / BK2)         // 24

__device__ __forceinline__ void gemm2_issue_loads(
    uint32_t sb, uint32_t stg, int tid, int m0, int n0, int k0,
    const __nv_bfloat16* Ah, const __nv_bfloat16* Al,
    const __nv_bfloat16* Bh, const __nv_bfloat16* Bl)
{
#pragma unroll
    for (int it = 0; it < 2; it++) {
        const int idx = tid + it * 256;
        {
            const int r = idx >> 2, c8 = (idx & 3) * 8;
            const size_t g = (size_t)(m0 + r) * D_MODEL + k0 + c8;
            const uint32_t so = (uint32_t)(r * LDA2 + c8) * 2;
            cp_async16(sb + stg + G2_AH + so, &Ah[g]);
            cp_async16(sb + stg + G2_AL + so, &Al[g]);
        }
        {
            const int r = idx >> 4, n8 = (idx & 15) * 8;
            const size_t g = (size_t)(k0 + r) * D_MODEL + n0 + n8;
            const uint32_t so = (uint32_t)(r * LDB2 + n8) * 2;
            cp_async16(sb + stg + G2_BH + so, &Bh[g]);
            cp_async16(sb + stg + G2_BL + so, &Bl[g]);
        }
    }
}

__device__ __forceinline__ void gemm2_compute_chunk(
    uint32_t sb, uint32_t stg, int lane, int wm, int wn, float c[2][8][4])
{
    const int a_row = lane & 15;
    const int a_kc  = (lane >> 4) * 8;
    const int b_k   = lane & 15;
    const int b_n   = (lane >> 4) * 8;
#pragma unroll
    for (int ks = 0; ks < BK2 / 16; ks++) {
        uint32_t ah0[4], ah1[4], al0[4], al1[4];
        {
            const uint32_t offH = stg + G2_AH +
                ((wm * 32 + a_row) * LDA2 + ks * 16 + a_kc) * 2;
            ldsm_x4(ah0, sb + offH);
            ldsm_x4(ah1, sb + offH + 16 * LDA2 * 2);
            const uint32_t offL = stg + G2_AL +
                ((wm * 32 + a_row) * LDA2 + ks * 16 + a_kc) * 2;
            ldsm_x4(al0, sb + offL);
            ldsm_x4(al1, sb + offL + 16 * LDA2 * 2);
        }
        // Load all B-hi frags first (16 regs)
        uint32_t bh[4][4];
#pragma unroll
        for (int nb = 0; nb < 4; nb++) {
            const uint32_t offB = stg + G2_BH +
                ((ks * 16 + b_k) * LDB2 + wn * 64 + nb * 16 + b_n) * 2;
            ldsm_x4_t(bh[nb], sb + offB);
        }
        // Pass 1: hi*hi — 16 MMAs, all distinct accumulators
#pragma unroll
        for (int nb = 0; nb < 4; nb++) {
            mma_bf16(c[0][2 * nb],     ah0, bh[nb][0], bh[nb][1]);
            mma_bf16(c[1][2 * nb],     ah1, bh[nb][0], bh[nb][1]);
            mma_bf16(c[0][2 * nb + 1], ah0, bh[nb][2], bh[nb][3]);
            mma_bf16(c[1][2 * nb + 1], ah1, bh[nb][2], bh[nb][3]);
        }
        // Pass 2: lo*hi — 16 MMAs, distinct
#pragma unroll
        for (int nb = 0; nb < 4; nb++) {
            mma_bf16(c[0][2 * nb],     al0, bh[nb][0], bh[nb][1]);
            mma_bf16(c[1][2 * nb],     al1, bh[nb][0], bh[nb][1]);
            mma_bf16(c[0][2 * nb + 1], al0, bh[nb][2], bh[nb][3]);
            mma_bf16(c[1][2 * nb + 1], al1, bh[nb][2], bh[nb][3]);
        }
        // Pass 3: hi*lo — lazy B-lo loads, distance 4
#pragma unroll
        for (int nb = 0; nb < 4; nb++) {
            uint32_t bl[4];
            const uint32_t offB = stg + G2_BL +
                ((ks * 16 + b_k) * LDB2 + wn * 64 + nb * 16 + b_n) * 2;
            ldsm_x4_t(bl, sb + offB);
            mma_bf16(c[0][2 * nb],     ah0, bl[0], bl[1]);
            mma_bf16(c[1][2 * nb],     ah1, bl[0], bl[1]);
            mma_bf16(c[0][2 * nb + 1], ah0, bl[2], bl[3]);
            mma_bf16(c[1][2 * nb + 1], ah1, bl[2], bl[3]);
        }
    }
}

// Fused QKV GEMM: blockIdx.z selects {Wq->Q(*ALPHA_Q), Wk->K, Wv->V}.
__global__ __launch_bounds__(256, 2) void gemm_qkv_kernel(
    const __nv_bfloat16* __restrict__ Ah, const __nv_bfloat16* __restrict__ Al,
    const __nv_bfloat16* __restrict__ whb, const __nv_bfloat16* __restrict__ wlb,
    const float* __restrict__ bq, const float* __restrict__ bk,
    const float* __restrict__ bv,
    __nv_bfloat16* __restrict__ qh, __nv_bfloat16* __restrict__ ql,
    __nv_bfloat16* __restrict__ kh, __nv_bfloat16* __restrict__ kl,
    __nv_bfloat16* __restrict__ vh, __nv_bfloat16* __restrict__ vl)
{
    extern __shared__ char smg[];
    const uint32_t sb = smem_to_u32(smg);
    const int tid  = threadIdx.x;
    const int lane = tid & 31;
    const int w    = tid >> 5;
    const int wm   = w & 3;
    const int wn   = w >> 2;
    const int m0   = blockIdx.x * BM2;
    const int n0   = blockIdx.y * BN2;
    const int z    = blockIdx.z;

    const __nv_bfloat16* Bh = whb + (size_t)z * W_ELEMS;
    const __nv_bfloat16* Bl = wlb + (size_t)z * W_ELEMS;
    const float* bias = (z == 0) ? bq : (z == 1) ? bk : bv;
    const float alpha = (z == 0) ? ALPHA_Q : 1.0f;
    __nv_bfloat16* Ch = (z == 0) ? qh : (z == 1) ? kh : vh;
    __nv_bfloat16* Cl = (z == 0) ? ql : (z == 1) ? kl : vl;

    float c[2][8][4];
#pragma unroll
    for (int mt = 0; mt < 2; mt++)
#pragma unroll
        for (int nt = 0; nt < 8; nt++)
#pragma unroll
            for (int j = 0; j < 4; j++) c[mt][nt][j] = 0.0f;

    gemm2_issue_loads(sb, 0, tid, m0, n0, 0, Ah, Al, Bh, Bl);
    CP_COMMIT();

    for (int ch = 0; ch < NCH2; ch++) {
        const uint32_t cur = (ch & 1) * G2_STAGE;
        if (ch + 1 < NCH2) {
            gemm2_issue_loads(sb, cur ^ G2_STAGE, tid, m0, n0,
                              (ch + 1) * BK2, Ah, Al, Bh, Bl);
            CP_COMMIT();
            CP_WAIT1();
        } else {
            CP_WAIT0();
        }
        __syncthreads();
        gemm2_compute_chunk(sb, cur, lane, wm, wn, c);
        __syncthreads();
    }

#pragma unroll
    for (int mt = 0; mt < 2; mt++) {
        const int mrow = m0 + wm * 32 + mt * 16 + (lane >> 2);
#pragma unroll
        for (int nt = 0; nt < 8; nt++) {
            const int ncol = n0 + wn * 64 + nt * 8 + (lane & 3) * 2;
            const float b0 = bias[ncol], b1 = bias[ncol + 1];
            const float v00 = alpha * (c[mt][nt][0] + b0);
            const float v01 = alpha * (c[mt][nt][1] + b1);
            const float v10 = alpha * (c[mt][nt][2] + b0);
            const float v11 = alpha * (c[mt][nt][3] + b1);
            const size_t g0 = (size_t)mrow * D_MODEL + ncol;
            const size_t g1 = (size_t)(mrow + 8) * D_MODEL + ncol;
            *reinterpret_cast<uint32_t*>(&Ch[g0]) = cvt_bf16x2(v00, v01);
            *reinterpret_cast<uint32_t*>(&Ch[g1]) = cvt_bf16x2(v10, v11);
            *reinterpret_cast<uint32_t*>(&Cl[g0]) =
                cvt_bf16x2(v00 - bf16_rt(v00), v01 - bf16_rt(v01));
            *reinterpret_cast<uint32_t*>(&Cl[g1]) =
                cvt_bf16x2(v10 - bf16_rt(v10), v11 - bf16_rt(v11));
        }
    }
}

// ===========================================================================
// O-projection GEMM: BM=64 x BN=128 (384 CTAs for better wave packing).
// 8 warps 2(M)x4(N), warp tile 32x32. Same 3-pass MMA order.
// Stage: AH|AL (64x40) + BH|BL (32x136) = 27648 B; x2 = 55296 B.
// ===========================================================================
#define GO_AH 0
#define GO_AL 5120
#define GO_BH 10240
#define GO_BL 18944
#define GO_STAGE 27648
#define SM_GO_TOTAL (2 * GO_STAGE)   // 55296

__device__ __forceinline__ void gemmo_issue_loads(
    uint32_t sb, uint32_t stg, int tid, int m0, int n0, int k0,
    const __nv_bfloat16* Ah, const __nv_bfloat16* Al,
    const __nv_bfloat16* Bh, const __nv_bfloat16* Bl)
{
    // A: 64 rows x 32 k -> 256 uint4; 1 per thread
    {
        const int r = tid >> 2, c8 = (tid & 3) * 8;
        const size_t g = (size_t)(m0 + r) * D_MODEL + k0 + c8;
        const uint32_t so = (uint32_t)(r * LDA2 + c8) * 2;
        cp_async16(sb + stg + GO_AH + so, &Ah[g]);
        cp_async16(sb + stg + GO_AL + so, &Al[g]);
    }
    // B: 32 k x 128 n -> 512 uint4; 2 per thread
#pragma unroll
    for (int it = 0; it < 2; it++) {
        const int idx = tid + it * 256;
        const int r = idx >> 4, n8 = (idx & 15) * 8;
        const size_t g = (size_t)(k0 + r) * D_MODEL + n0 + n8;
        const uint32_t so = (uint32_t)(r * LDB2 + n8) * 2;
        cp_async16(sb + stg + GO_BH + so, &Bh[g]);
        cp_async16(sb + stg + GO_BL + so, &Bl[g]);
    }
}

__global__ __launch_bounds__(256, 2) void gemm_o_kernel(
    const __nv_bfloat16* __restrict__ Ah, const __nv_bfloat16* __restrict__ Al,
    const __nv_bfloat16* __restrict__ Bh, const __nv_bfloat16* __restrict__ Bl,
    const float* __restrict__ bias, float* __restrict__ Cf)
{
    extern __shared__ char smg[];
    const uint32_t sb = smem_to_u32(smg);
    const int tid  = threadIdx.x;
    const int lane = tid & 31;
    const int w    = tid >> 5;
    const int wm   = w & 1;          // 2 M-warps
    const int wn   = w >> 1;         // 4 N-warps
    const int m0   = blockIdx.x * 64;
    const int n0   = blockIdx.y * BN2;

    const int a_row = lane & 15;
    const int a_kc  = (lane >> 4) * 8;
    const int b_k   = lane & 15;
    const int b_n   = (lane >> 4) * 8;

    float c[2][4][4];
#pragma unroll
    for (int mt = 0; mt < 2; mt++)
#pragma unroll
        for (int nt = 0; nt < 4; nt++)
#pragma unroll
            for (int j = 0; j < 4; j++) c[mt][nt][j] = 0.0f;

    gemmo_issue_loads(sb, 0, tid, m0, n0, 0, Ah, Al, Bh, Bl);
    CP_COMMIT();

    for (int ch = 0; ch < NCH2; ch++) {
        const uint32_t cur = (ch & 1) * GO_STAGE;
        if (ch + 1 < NCH2) {
            gemmo_issue_loads(sb, cur ^ GO_STAGE, tid, m0, n0,
                              (ch + 1) * BK2, Ah, Al, Bh, Bl);
            CP_COMMIT();
            CP_WAIT1();
        } else {
            CP_WAIT0();
        }
        __syncthreads();

#pragma unroll
        for (int ks = 0; ks < BK2 / 16; ks++) {
            uint32_t ah0[4], ah1[4], al0[4], al1[4];
            {
                const uint32_t offH = cur + GO_AH +
                    ((wm * 32 + a_row) * LDA2 + ks * 16 + a_kc) * 2;
                ldsm_x4(ah0, sb + offH);
                ldsm_x4(ah1, sb + offH + 16 * LDA2 * 2);
                const uint32_t offL = cur + GO_AL +
                    ((wm * 32 + a_row) * LDA2 + ks * 16 + a_kc) * 2;
                ldsm_x4(al0, sb + offL);
                ldsm_x4(al1, sb + offL + 16 * LDA2 * 2);
            }
            uint32_t bh[2][4];
#pragma unroll
            for (int nb = 0; nb < 2; nb++) {
                const uint32_t offB = cur + GO_BH +
                    ((ks * 16 + b_k) * LDB2 + wn * 32 + nb * 16 + b_n) * 2;
                ldsm_x4_t(bh[nb], sb + offB);
            }
            // Pass 1: hi*hi — 8 distinct accs
#pragma unroll
            for (int nb = 0; nb < 2; nb++) {
                mma_bf16(c[0][2 * nb],     ah0, bh[nb][0], bh[nb][1]);
                mma_bf16(c[1][2 * nb],     ah1, bh[nb][0], bh[nb][1]);
                mma_bf16(c[0][2 * nb + 1], ah0, bh[nb][2], bh[nb][3]);
                mma_bf16(c[1][2 * nb + 1], ah1, bh[nb][2], bh[nb][3]);
            }
            // Pass 2: lo*hi
#pragma unroll
            for (int nb = 0; nb < 2; nb++) {
                mma_bf16(c[0][2 * nb],     al0, bh[nb][0], bh[nb][1]);
                mma_bf16(c[1][2 * nb],     al1, bh[nb][0], bh[nb][1]);
                mma_bf16(c[0][2 * nb + 1], al0, bh[nb][2], bh[nb][3]);
                mma_bf16(c[1][2 * nb + 1], al1, bh[nb][2], bh[nb][3]);
            }
            // Pass 3: hi*lo
#pragma unroll
            for (int nb = 0; nb < 2; nb++) {
                uint32_t bl[4];
                const uint32_t offB = cur + GO_BL +
                    ((ks * 16 + b_k) * LDB2 + wn * 32 + nb * 16 + b_n) * 2;
                ldsm_x4_t(bl, sb + offB);
                mma_bf16(c[0][2 * nb],     ah0, bl[0], bl[1]);
                mma_bf16(c[1][2 * nb],     ah1, bl[0], bl[1]);
                mma_bf16(c[0][2 * nb + 1], ah0, bl[2], bl[3]);
                mma_bf16(c[1][2 * nb + 1], ah1, bl[2], bl[3]);
            }
        }
        __syncthreads();
    }

#pragma unroll
    for (int mt = 0; mt < 2; mt++) {
        const int mrow = m0 + wm * 32 + mt * 16 + (lane >> 2);
#pragma unroll
        for (int nt = 0; nt < 4; nt++) {
            const int ncol = n0 + wn * 32 + nt * 8 + (lane & 3) * 2;
            const float b0 = bias[ncol], b1 = bias[ncol + 1];
            float2 o0 = make_float2(c[mt][nt][0] + b0, c[mt][nt][1] + b1);
            float2 o1 = make_float2(c[mt][nt][2] + b0, c[mt][nt][3] + b1);
            *reinterpret_cast<float2*>(&Cf[(size_t)mrow * D_MODEL + ncol]) = o0;
            *reinterpret_cast<float2*>(&Cf[(size_t)(mrow + 8) * D_MODEL + ncol]) = o1;
        }
    }
}

// ===========================================================================
// HMMA flash attention, 2-stage cp.async pipeline; exp2-domain softmax.
// MMA order alternates S/ctx tiles (dep distance 2, per-acc order unchanged).
// ===========================================================================
#define AT_LD 72
#define A_QH 0
#define A_QL 18432
#define A_QSZ 36864
#define A_KH 0
#define A_KL 9216
#define A_VH 18432
#define A_VL 27648
#define A_STAGE 36864
#define A_SM_TOTAL (A_QSZ + 2 * A_STAGE)   // 110592

__device__ __forceinline__ void attn_issue_loads(
    uint32_t sb, uint32_t stg, int tid, size_t rbase, int kt, int hcol,
    const __nv_bfloat16* Kh, const __nv_bfloat16* Kl,
    const __nv_bfloat16* Vh, const __nv_bfloat16* Vl)
{
    const int r  = tid >> 3;
    const int c8 = (tid & 7) * 8;
#pragma unroll
    for (int it = 0; it < 2; it++) {
        const int rr = r + it * 32;
        const size_t g = (rbase + kt + rr) * D_MODEL + hcol + c8;
        const uint32_t so = (uint32_t)(rr * AT_LD + c8) * 2;
        cp_async16(sb + stg + A_KH + so, &Kh[g]);
        cp_async16(sb + stg + A_KL + so, &Kl[g]);
        cp_async16(sb + stg + A_VH + so, &Vh[g]);
        cp_async16(sb + stg + A_VL + so, &Vl[g]);
    }
}

__global__ __launch_bounds__(256, 2) void attn_hmma_kernel(
    const __nv_bfloat16* __restrict__ Qh, const __nv_bfloat16* __restrict__ Ql,
    const __nv_bfloat16* __restrict__ Kh, const __nv_bfloat16* __restrict__ Kl,
    const __nv_bfloat16* __restrict__ Vh, const __nv_bfloat16* __restrict__ Vl,
    __nv_bfloat16* __restrict__ Ch, __nv_bfloat16* __restrict__ Cl)
{
    extern __shared__ char sma[];
    const uint32_t sb = smem_to_u32(sma);
    const int tid  = threadIdx.x;
    const int lane = tid & 31;
    const int w    = tid >> 5;
    const int q0   = blockIdx.x * 128;
    const int h    = blockIdx.y;
    const int b    = blockIdx.z;
    const int hcol = h * HD;
    const size_t rbase = (size_t)b * S_LEN;

    const int l_row = lane & 15;
    const int l_c8  = (lane >> 4) * 8;

    attn_issue_loads(sb, A_QSZ, tid, rbase, 0, hcol, Kh, Kl, Vh, Vl);
    CP_COMMIT();

    {
        const int r = tid >> 3;
        const int c8 = (tid & 7) * 8;
#pragma unroll
        for (int it = 0; it < 4; it++) {
            const int rr = r + it * 32;
            const size_t g = (rbase + q0 + rr) * D_MODEL + hcol + c8;
            *reinterpret_cast<uint4*>(sma + A_QH + (rr * AT_LD + c8) * 2) =
                *reinterpret_cast<const uint4*>(&Qh[g]);
            *reinterpret_cast<uint4*>(sma + A_QL + (rr * AT_LD + c8) * 2) =
                *reinterpret_cast<const uint4*>(&Ql[g]);
        }
    }

    float ctx[8][4];
#pragma unroll
    for (int nt = 0; nt < 8; nt++)
#pragma unroll
        for (int j = 0; j < 4; j++) ctx[nt][j] = 0.0f;
    float m0r = -INFINITY, m1r = -INFINITY, l0r = 0.0f, l1r = 0.0f;

    const int NT = S_LEN / 64;
    for (int ti = 0; ti < NT; ti++) {
        const uint32_t cur = A_QSZ + (ti & 1) * A_STAGE;
        if (ti + 1 < NT) {
            attn_issue_loads(sb, A_QSZ + ((ti + 1) & 1) * A_STAGE,
                             tid, rbase, (ti + 1) * 64, hcol, Kh, Kl, Vh, Vl);
            CP_COMMIT();
            CP_WAIT1();
        } else {
            CP_WAIT0();
        }
        __syncthreads();

        // ---- S = Q K^T, 3-term split, alternated tiles
        float S[8][4];
#pragma unroll
        for (int nt = 0; nt < 8; nt++)
#pragma unroll
            for (int j = 0; j < 4; j++) S[nt][j] = 0.0f;

#pragma unroll
        for (int ks = 0; ks < 4; ks++) {
            uint32_t qh[4], ql[4];
            const uint32_t qoff = ((w * 16 + l_row) * AT_LD + ks * 16 + l_c8) * 2;
            ldsm_x4(qh, sb + A_QH + qoff);
            ldsm_x4(ql, sb + A_QL + qoff);
#pragma unroll
            for (int g = 0; g < 4; g++) {
                uint32_t kh[4], kl[4];
                const uint32_t koff = cur + A_KH +
                    ((g * 16 + l_row) * AT_LD + ks * 16 + l_c8) * 2;
                ldsm_x4(kh, sb + koff);
                ldsm_x4(kl, sb + koff + (A_KL - A_KH));
                mma_bf16(S[2 * g],     qh, kh[0], kh[2]);
                mma_bf16(S[2 * g + 1], qh, kh[1], kh[3]);
                mma_bf16(S[2 * g],     ql, kh[0], kh[2]);
                mma_bf16(S[2 * g + 1], ql, kh[1], kh[3]);
                mma_bf16(S[2 * g],     qh, kl[0], kl[2]);
                mma_bf16(S[2 * g + 1], qh, kl[1], kl[3]);
            }
        }

        // ---- online softmax (exp2 domain)
        float mx0 = -INFINITY, mx1 = -INFINITY;
#pragma unroll
        for (int nt = 0; nt < 8; nt++) {
            mx0 = fmaxf(mx0, fmaxf(S[nt][0], S[nt][1]));
            mx1 = fmaxf(mx1, fmaxf(S[nt][2], S[nt][3]));
        }
        mx0 = fmaxf(mx0, __shfl_xor_sync(0xffffffffu, mx0, 1));
        mx0 = fmaxf(mx0, __shfl_xor_sync(0xffffffffu, mx0, 2));
        mx1 = fmaxf(mx1, __shfl_xor_sync(0xffffffffu, mx1, 1));
        mx1 = fmaxf(mx1, __shfl_xor_sync(0xffffffffu, mx1, 2));
        const float mn0 = fmaxf(m0r, mx0);
        const float mn1 = fmaxf(m1r, mx1);
        const float cr0 = exp2f(m0r - mn0);
        const float cr1 = exp2f(m1r - mn1);
        float s0 = 0.0f, s1 = 0.0f;
#pragma unroll
        for (int nt = 0; nt < 8; nt++) {
            S[nt][0] = exp2f(S[nt][0] - mn0);
            S[nt][1] = exp2f(S[nt][1] - mn0);
            S[nt][2] = exp2f(S[nt][2] - mn1);
            S[nt][3] = exp2f(S[nt][3] - mn1);
            s0 += S[nt][0] + S[nt][1];
            s1 += S[nt][2] + S[nt][3];
            ctx[nt][0] *= cr0; ctx[nt][1] *= cr0;
            ctx[nt][2] *= cr1; ctx[nt][3] *= cr1;
        }
        s0 += __shfl_xor_sync(0xffffffffu, s0, 1);
        s0 += __shfl_xor_sync(0xffffffffu, s0, 2);
        s1 += __shfl_xor_sync(0xffffffffu, s1, 1);
        s1 += __shfl_xor_sync(0xffffffffu, s1, 2);
        l0r = l0r * cr0 + s0;
        l1r = l1r * cr1 + s1;
        m0r = mn0;
        m1r = mn1;

        // ---- pack P into a-frags (hi + lo)
        uint32_t ph[4][4], pl[4][4];
#pragma unroll
        for (int j = 0; j < 4; j++) {
            const float p0 = S[2 * j][0],     p1 = S[2 * j][1];
            const float p2 = S[2 * j][2],     p3 = S[2 * j][3];
            const float p4 = S[2 * j + 1][0], p5 = S[2 * j + 1][1];
            const float p6 = S[2 * j + 1][2], p7 = S[2 * j + 1][3];
            ph[j][0] = cvt_bf16x2(p0, p1);
            ph[j][1] = cvt_bf16x2(p2, p3);
            ph[j][2] = cvt_bf16x2(p4, p5);
            ph[j][3] = cvt_bf16x2(p6, p7);
            pl[j][0] = cvt_bf16x2(p0 - bf16_rt(p0), p1 - bf16_rt(p1));
            pl[j][1] = cvt_bf16x2(p2 - bf16_rt(p2), p3 - bf16_rt(p3));
            pl[j][2] = cvt_bf16x2(p4 - bf16_rt(p4), p5 - bf16_rt(p5));
            pl[j][3] = cvt_bf16x2(p6 - bf16_rt(p6), p7 - bf16_rt(p7));
        }

        // ---- ctx += P V, alternated tiles
#pragma unroll
        for (int kc = 0; kc < 4; kc++) {
#pragma unroll
            for (int dg = 0; dg < 4; dg++) {
                uint32_t vh[4], vl[4];
                const uint32_t voff = cur + A_VH +
                    ((kc * 16 + l_row) * AT_LD + dg * 16 + l_c8) * 2;
                ldsm_x4_t(vh, sb + voff);
                ldsm_x4_t(vl, sb + voff + (A_VL - A_VH));
                mma_bf16(ctx[2 * dg],     ph[kc], vh[0], vh[1]);
                mma_bf16(ctx[2 * dg + 1], ph[kc], vh[2], vh[3]);
                mma_bf16(ctx[2 * dg],     pl[kc], vh[0], vh[1]);
                mma_bf16(ctx[2 * dg + 1], pl[kc], vh[2], vh[3]);
                mma_bf16(ctx[2 * dg],     ph[kc], vl[0], vl[1]);
                mma_bf16(ctx[2 * dg + 1], ph[kc], vl[2], vl[3]);
            }
        }
        __syncthreads();
    }

    // ---- epilogue
    const float inv0 = 1.0f / l0r;
    const float inv1 = 1.0f / l1r;
    const int row0 = q0 + w * 16 + (lane >> 2);
#pragma unroll
    for (int nt = 0; nt < 8; nt++) {
        const int col = hcol + nt * 8 + (lane & 3) * 2;
        const float v00 = ctx[nt][0] * inv0, v01 = ctx[nt][1] * inv0;
        const float v10 = ctx[nt][2] * inv1, v11 = ctx[nt][3] * inv1;
        const size_t g0 = (rbase + row0) * D_MODEL + col;
        const size_t g1 = (rbase + row0 + 8) * D_MODEL + col;
        *reinterpret_cast<uint32_t*>(&Ch[g0]) = cvt_bf16x2(v00, v01);
        *reinterpret_cast<uint32_t*>(&Ch[g1]) = cvt_bf16x2(v10, v11);
        *reinterpret_cast<uint32_t*>(&Cl[g0]) =
            cvt_bf16x2(v00 - bf16_rt(v00), v01 - bf16_rt(v01));
        *reinterpret_cast<uint32_t*>(&Cl[g1]) =
            cvt_bf16x2(v10 - bf16_rt(v10), v11 - bf16_rt(v11));
    }
}

// ---------------------------------------------------------------------------
// Launch
// ---------------------------------------------------------------------------
extern "C" void kernel_launch(void* const* d_in, const int* in_sizes, int n_in,
                              void* d_out, int out_size)
{
    const float* x  = (const float*)d_in[0];
    const float* Wq = (const float*)d_in[1];
    const float* bq = (const float*)d_in[2];
    const float* Wk = (const float*)d_in[3];
    const float* bk = (const float*)d_in[4];
    const float* Wv = (const float*)d_in[5];
    const float* bv = (const float*)d_in[6];
    const float* Wo = (const float*)d_in[7];
    const float* bo = (const float*)d_in[8];
    float* out = (float*)d_out;

    __nv_bfloat16 *xh, *xl, *wh, *wl, *qh, *ql, *kh, *kl, *vh, *vl, *ch, *cl;
    cudaGetSymbolAddress((void**)&xh, g_xh);
    cudaGetSymbolAddress((void**)&xl, g_xl);
    cudaGetSymbolAddress((void**)&wh, g_wh);
    cudaGetSymbolAddress((void**)&wl, g_wl);
    cudaGetSymbolAddress((void**)&qh, g_qh);
    cudaGetSymbolAddress((void**)&ql, g_ql);
    cudaGetSymbolAddress((void**)&kh, g_kh);
    cudaGetSymbolAddress((void**)&kl, g_kl);
    cudaGetSymbolAddress((void**)&vh, g_vh);
    cudaGetSymbolAddress((void**)&vl, g_vl);
    cudaGetSymbolAddress((void**)&ch, g_ch);
    cudaGetSymbolAddress((void**)&cl, g_cl);

    cudaFuncSetAttribute(gemm_qkv_kernel,
                         cudaFuncAttributeMaxDynamicSharedMemorySize,
                         SM_G2_TOTAL);
    cudaFuncSetAttribute(gemm_o_kernel,
                         cudaFuncAttributeMaxDynamicSharedMemorySize,
                         SM_GO_TOTAL);
    cudaFuncSetAttribute(attn_hmma_kernel,
                         cudaFuncAttributeMaxDynamicSharedMemorySize,
                         A_SM_TOTAL);

    dim3 split_grid((M_ROWS * D_MODEL / 4 + 255) / 256, 5);
    split_all_kernel<<<split_grid, 256>>>(x, Wq, Wk, Wv, Wo, xh, xl, wh, wl);

    dim3 qkv_grid(M_ROWS / BM2, D_MODEL / BN2, 3);   // 32 x 6 x 3
    gemm_qkv_kernel<<<qkv_grid, 256, SM_G2_TOTAL>>>(
        xh, xl, wh, wl, bq, bk, bv, qh, ql, kh, kl, vh, vl);

    dim3 attn_grid(S_LEN / 128, H_NUM, B_SZ);        // 16 x 12 x 2
    attn_hmma_kernel<<<attn_grid, 256, A_SM_TOTAL>>>(
        qh, ql, kh, kl, vh, vl, ch, cl);

    dim3 o_grid(M_ROWS / 64, D_MODEL / BN2);         // 64 x 6
    gemm_o_kernel<<<o_grid, 256, SM_GO_TOTAL>>>(
        ch, cl, wh + 3 * W_ELEMS, wl + 3 * W_ELEMS, bo, out);
}